// round 2
// baseline (speedup 1.0000x reference)
#include <cuda_runtime.h>
#include <cuda_bf16.h>
#include <cstdint>

// Problem constants
#define S_   2048
#define D_   2048
#define H_   32
#define KVH_ 8
#define HD_  64
#define KD_  512   // KVH*HD
#define EPS_ 1e-5f

// ---------------------------------------------------------------------------
// Scratch (no allocations allowed -> __device__ globals)
// ---------------------------------------------------------------------------
__device__ float g_q[S_ * D_];     // q after proj / rmsnorm+rope
__device__ float g_k[S_ * KD_];    // k after proj / rmsnorm+rope
__device__ float g_v[S_ * KD_];    // v
__device__ float g_att[S_ * D_];   // attention output (S, H*HD)

// ---------------------------------------------------------------------------
// SGEMM: C[M,N] = A[M,K] @ B[K,N], row-major, fp32.
// 128x128 block tile, BK=16, 256 threads, 8x8 register microtile.
// ---------------------------------------------------------------------------
#define BM 128
#define BN 128
#define BK 16
#define TM 8
#define TN 8

__global__ __launch_bounds__(256) void sgemm_kernel(
    const float* __restrict__ A, const float* __restrict__ B,
    float* __restrict__ C, int M, int N, int K)
{
    __shared__ float As[BK][BM];
    __shared__ float Bs[BK][BN];

    const int tid  = threadIdx.x;
    const int brow = blockIdx.y * BM;
    const int bcol = blockIdx.x * BN;
    const int ty = tid >> 4;          // 0..15
    const int tx = tid & 15;          // 0..15

    // A-tile load mapping: 128x16 = 512 float4, 2 per thread
    const int a_r = tid >> 2;         // 0..63
    const int a_c = (tid & 3) * 4;    // 0,4,8,12
    // B-tile load mapping: 16x128 = 512 float4, 2 per thread
    const int b_r = tid >> 5;         // 0..7
    const int b_c = (tid & 31) * 4;   // 0..124

    float acc[TM][TN] = {};

    for (int k0 = 0; k0 < K; k0 += BK) {
        #pragma unroll
        for (int i = 0; i < 2; i++) {
            int r = a_r + i * 64;
            float4 v = *(const float4*)&A[(size_t)(brow + r) * K + k0 + a_c];
            As[a_c + 0][r] = v.x;
            As[a_c + 1][r] = v.y;
            As[a_c + 2][r] = v.z;
            As[a_c + 3][r] = v.w;
        }
        #pragma unroll
        for (int i = 0; i < 2; i++) {
            int r = b_r + i * 8;
            *(float4*)&Bs[r][b_c] = *(const float4*)&B[(size_t)(k0 + r) * N + bcol + b_c];
        }
        __syncthreads();

        #pragma unroll
        for (int kk = 0; kk < BK; kk++) {
            float ar[TM], br[TN];
            #pragma unroll
            for (int i = 0; i < TM; i += 4) {
                float4 v = *(const float4*)&As[kk][ty * TM + i];
                ar[i] = v.x; ar[i+1] = v.y; ar[i+2] = v.z; ar[i+3] = v.w;
            }
            #pragma unroll
            for (int j = 0; j < TN; j += 4) {
                float4 v = *(const float4*)&Bs[kk][tx * TN + j];
                br[j] = v.x; br[j+1] = v.y; br[j+2] = v.z; br[j+3] = v.w;
            }
            #pragma unroll
            for (int i = 0; i < TM; i++)
                #pragma unroll
                for (int j = 0; j < TN; j++)
                    acc[i][j] += ar[i] * br[j];
        }
        __syncthreads();
    }

    #pragma unroll
    for (int i = 0; i < TM; i++) {
        int r = brow + ty * TM + i;
        #pragma unroll
        for (int j = 0; j < TN; j += 4) {
            *(float4*)&C[(size_t)r * N + bcol + tx * TN + j] =
                make_float4(acc[i][j], acc[i][j+1], acc[i][j+2], acc[i][j+3]);
        }
    }
}

// ---------------------------------------------------------------------------
// Fused rmsnorm (over full row width) + RoPE (per 64-wide head).
// One block per sequence row, 256 threads. In-place.
// ---------------------------------------------------------------------------
__global__ __launch_bounds__(256) void rms_rope_kernel(
    float* __restrict__ buf, const float* __restrict__ w,
    const float* __restrict__ cosp, const float* __restrict__ sinp, int width)
{
    const int s = blockIdx.x;
    float* row = buf + (size_t)s * width;
    const int tid = threadIdx.x;

    float ss = 0.f;
    for (int i = tid; i < width; i += 256) {
        float v = row[i];
        ss += v * v;
    }
    #pragma unroll
    for (int o = 16; o; o >>= 1) ss += __shfl_xor_sync(0xffffffffu, ss, o);

    __shared__ float red[8];
    __shared__ float s_r;
    if ((tid & 31) == 0) red[tid >> 5] = ss;
    __syncthreads();
    if (tid == 0) {
        float t = 0.f;
        #pragma unroll
        for (int i = 0; i < 8; i++) t += red[i];
        s_r = rsqrtf(t / (float)width + EPS_);
    }
    __syncthreads();
    const float r = s_r;

    const float* cr = cosp + (size_t)s * HD_;
    const float* sr = sinp + (size_t)s * HD_;
    const int npairs = width >> 1;
    for (int p = tid; p < npairs; p += 256) {
        int head = p >> 5;            // 32 pairs per head
        int d    = p & 31;
        int i0 = head * HD_ + d;
        int i1 = i0 + 32;
        float v0 = row[i0] * r * w[i0];
        float v1 = row[i1] * r * w[i1];
        float c0 = cr[d],      s0 = sr[d];
        float c1 = cr[d + 32], s1 = sr[d + 32];
        row[i0] = v0 * c0 - v1 * s0;   // x1*cos - x2*sin
        row[i1] = v1 * c1 + v0 * s1;   // x2*cos + x1*sin
    }
}

// ---------------------------------------------------------------------------
// Flash attention, fp32, causal, GQA (4 q-heads per kv-head).
// grid = (S/64, H). 256 threads. 64x64 q/kv tiles, online softmax.
// smem: Qst [d][m], KP (K-tile [d][n] then P-tile [m][n] union), Vs [n][d]
//  -> exactly 48 KB static.
// ---------------------------------------------------------------------------
#define FA_BM 64
#define FA_BN 64

__global__ __launch_bounds__(256) void flash_kernel(
    const float* __restrict__ Q, const float* __restrict__ K,
    const float* __restrict__ V, float* __restrict__ O)
{
    __shared__ float Qst[HD_][FA_BM];     // [d][m]
    __shared__ float KP[FA_BN][FA_BM];    // K as [d][n]; reused as P [m][n]
    __shared__ float Vs[FA_BN][HD_];      // [n][d]

    const int tid = threadIdx.x;
    const int ty = tid >> 4;              // 0..15 -> 4 q rows
    const int tx = tid & 15;              // 0..15 -> 4 cols
    const int q0 = blockIdx.x * FA_BM;
    const int h  = blockIdx.y;
    const int kh = h >> 2;                // N_REP = 4

    // Load Q tile transposed: Qst[d][m]
    {
        int m  = tid >> 2;
        int d0 = (tid & 3) * 16;
        const float* qrow = Q + (size_t)(q0 + m) * D_ + h * HD_;
        #pragma unroll
        for (int i = 0; i < 4; i++) {
            float4 v = *(const float4*)(qrow + d0 + 4 * i);
            Qst[d0 + 4*i + 0][m] = v.x;
            Qst[d0 + 4*i + 1][m] = v.y;
            Qst[d0 + 4*i + 2][m] = v.z;
            Qst[d0 + 4*i + 3][m] = v.w;
        }
    }

    float acc[4][4] = {};
    float mrow[4], lrow[4];
    #pragma unroll
    for (int i = 0; i < 4; i++) { mrow[i] = -1e30f; lrow[i] = 0.f; }

    const float scale = 0.125f;           // HD^-0.5
    const int n_end = q0 + FA_BM;

    for (int n0 = 0; n0 < n_end; n0 += FA_BN) {
        // Load K tile transposed into KP[d][n]; V tile natural into Vs[n][d]
        {
            int n  = tid >> 2;
            int d0 = (tid & 3) * 16;
            const float* krow = K + (size_t)(n0 + n) * KD_ + kh * HD_;
            const float* vrow = V + (size_t)(n0 + n) * KD_ + kh * HD_;
            #pragma unroll
            for (int i = 0; i < 4; i++) {
                float4 kv = *(const float4*)(krow + d0 + 4 * i);
                KP[d0 + 4*i + 0][n] = kv.x;
                KP[d0 + 4*i + 1][n] = kv.y;
                KP[d0 + 4*i + 2][n] = kv.z;
                KP[d0 + 4*i + 3][n] = kv.w;
                *(float4*)&Vs[n][d0 + 4*i] = *(const float4*)(vrow + d0 + 4*i);
            }
        }
        __syncthreads();

        // S = Q K^T (64x64), microtile 4x4
        float sreg[4][4] = {};
        #pragma unroll
        for (int kk = 0; kk < HD_; kk++) {
            float ar[4], br[4];
            float4 av = *(const float4*)&Qst[kk][ty * 4];
            ar[0] = av.x; ar[1] = av.y; ar[2] = av.z; ar[3] = av.w;
            float4 bv = *(const float4*)&KP[kk][tx * 4];
            br[0] = bv.x; br[1] = bv.y; br[2] = bv.z; br[3] = bv.w;
            #pragma unroll
            for (int i = 0; i < 4; i++)
                #pragma unroll
                for (int j = 0; j < 4; j++)
                    sreg[i][j] += ar[i] * br[j];
        }

        // scale + causal mask
        const bool diag = (n0 + FA_BN > q0);
        #pragma unroll
        for (int i = 0; i < 4; i++) {
            int rowg = q0 + ty * 4 + i;
            #pragma unroll
            for (int j = 0; j < 4; j++) {
                int colg = n0 + tx * 4 + j;
                float vv = sreg[i][j] * scale;
                if (diag && colg > rowg) vv = -1e30f;
                sreg[i][j] = vv;
            }
        }

        // online softmax per q row (row owners = 16 lanes with same ty)
        #pragma unroll
        for (int i = 0; i < 4; i++) {
            float tmax = sreg[i][0];
            #pragma unroll
            for (int j = 1; j < 4; j++) tmax = fmaxf(tmax, sreg[i][j]);
            #pragma unroll
            for (int o = 8; o; o >>= 1)
                tmax = fmaxf(tmax, __shfl_xor_sync(0xffffffffu, tmax, o));
            float mnew = fmaxf(mrow[i], tmax);
            float corr = __expf(mrow[i] - mnew);
            float rsum = 0.f;
            #pragma unroll
            for (int j = 0; j < 4; j++) {
                float p = __expf(sreg[i][j] - mnew);
                sreg[i][j] = p;
                rsum += p;
            }
            #pragma unroll
            for (int o = 8; o; o >>= 1)
                rsum += __shfl_xor_sync(0xffffffffu, rsum, o);
            lrow[i] = lrow[i] * corr + rsum;
            mrow[i] = mnew;
            #pragma unroll
            for (int j = 0; j < 4; j++) acc[i][j] *= corr;
        }

        __syncthreads();   // everyone done reading KP as K-tile

        // Write P into KP as [m][n]
        #pragma unroll
        for (int i = 0; i < 4; i++)
            *(float4*)&KP[ty * 4 + i][tx * 4] =
                make_float4(sreg[i][0], sreg[i][1], sreg[i][2], sreg[i][3]);
        __syncthreads();

        // O += P @ V
        #pragma unroll
        for (int kk = 0; kk < FA_BN; kk++) {
            float ar[4], br[4];
            #pragma unroll
            for (int i = 0; i < 4; i++) ar[i] = KP[ty * 4 + i][kk];
            float4 bv = *(const float4*)&Vs[kk][tx * 4];
            br[0] = bv.x; br[1] = bv.y; br[2] = bv.z; br[3] = bv.w;
            #pragma unroll
            for (int i = 0; i < 4; i++)
                #pragma unroll
                for (int j = 0; j < 4; j++)
                    acc[i][j] += ar[i] * br[j];
        }
        __syncthreads();   // before next tile overwrites KP/Vs
    }

    // finalize: divide by l, write out (S, H*HD)
    #pragma unroll
    for (int i = 0; i < 4; i++) {
        int rowg = q0 + ty * 4 + i;
        float inv = 1.f / lrow[i];
        #pragma unroll
        for (int j = 0; j < 4; j++)
            O[(size_t)rowg * D_ + h * HD_ + tx * 4 + j] = acc[i][j] * inv;
    }
}

// ---------------------------------------------------------------------------
// Launch
// ---------------------------------------------------------------------------
extern "C" void kernel_launch(void* const* d_in, const int* in_sizes, int n_in,
                              void* d_out, int out_size)
{
    const float* x    = (const float*)d_in[0];
    const float* cosp = (const float*)d_in[1];
    const float* sinp = (const float*)d_in[2];
    // d_in[3] = mask (causal tril, recomputed analytically) — unused
    const float* Wq   = (const float*)d_in[4];
    const float* Wk   = (const float*)d_in[5];
    const float* Wv   = (const float*)d_in[6];
    const float* Wo   = (const float*)d_in[7];
    const float* qn_w = (const float*)d_in[8];
    const float* kn_w = (const float*)d_in[9];
    float* out = (float*)d_out;

    float *qp, *kp, *vp, *ap;
    cudaGetSymbolAddress((void**)&qp, g_q);
    cudaGetSymbolAddress((void**)&kp, g_k);
    cudaGetSymbolAddress((void**)&vp, g_v);
    cudaGetSymbolAddress((void**)&ap, g_att);

    // Projections
    sgemm_kernel<<<dim3(D_ / BN, S_ / BM), 256>>>(x, Wq, qp, S_, D_, D_);
    sgemm_kernel<<<dim3(KD_ / BN, S_ / BM), 256>>>(x, Wk, kp, S_, KD_, D_);
    sgemm_kernel<<<dim3(KD_ / BN, S_ / BM), 256>>>(x, Wv, vp, S_, KD_, D_);

    // rmsnorm + RoPE (in place)
    rms_rope_kernel<<<S_, 256>>>(qp, qn_w, cosp, sinp, D_);
    rms_rope_kernel<<<S_, 256>>>(kp, kn_w, cosp, sinp, KD_);

    // Causal GQA flash attention
    flash_kernel<<<dim3(S_ / FA_BM, H_), 256>>>(qp, kp, vp, ap);

    // Output projection
    sgemm_kernel<<<dim3(D_ / BN, S_ / BM), 256>>>(ap, Wo, out, S_, D_, D_);
}

// round 6
// speedup vs baseline: 1.5357x; 1.5357x over previous
#include <cuda_runtime.h>
#include <cuda_bf16.h>
#include <cstdint>

// Problem constants
#define S_   2048
#define D_   2048
#define H_   32
#define KVH_ 8
#define HD_  64
#define KD_  512   // KVH*HD
#define EPS_ 1e-5f

// ---------------------------------------------------------------------------
// Scratch (no allocations allowed -> __device__ globals)
// ---------------------------------------------------------------------------
__device__ float g_q[S_ * D_];     // q after proj / rmsnorm+rope
__device__ float g_k[S_ * KD_];    // k after proj / rmsnorm+rope
__device__ float g_v[S_ * KD_];    // v
__device__ float g_att[S_ * D_];   // attention output (S, H*HD)

// ---------------------------------------------------------------------------
// TF32 tensor-core GEMM: C[M,N] = A[M,K] @ B[K,N], row-major fp32 in/out.
// 128x128 block tile, BK=32, 256 threads (8 warps, 2x4 grid, 64x32 warp tile).
// mma.sync.aligned.m16n8k8.row.col.f32.tf32.tf32.f32
// Inputs rounded to tf32 (cvt.rna) during smem staging.
// ---------------------------------------------------------------------------
#define GM 128
#define GN 128
#define GK 32
#define PAD 8   // row pad (words) -> fragment LDS hits 32 distinct banks

__device__ __forceinline__ uint32_t f2tf32(float x) {
    uint32_t r;
    asm("cvt.rna.tf32.f32 %0, %1;" : "=r"(r) : "f"(x));
    return r;
}

__device__ __forceinline__ void mma_tf32(
    float& c0, float& c1, float& c2, float& c3,
    uint32_t a0, uint32_t a1, uint32_t a2, uint32_t a3,
    uint32_t b0, uint32_t b1)
{
    asm volatile(
        "mma.sync.aligned.m16n8k8.row.col.f32.tf32.tf32.f32 "
        "{%0,%1,%2,%3}, {%4,%5,%6,%7}, {%8,%9}, {%0,%1,%2,%3};\n"
        : "+f"(c0), "+f"(c1), "+f"(c2), "+f"(c3)
        : "r"(a0), "r"(a1), "r"(a2), "r"(a3), "r"(b0), "r"(b1));
}

__global__ __launch_bounds__(256) void mma_gemm_kernel(
    const float* __restrict__ A, const float* __restrict__ B,
    float* __restrict__ C, int M, int N, int K)
{
    __shared__ uint32_t As[GK][GM + PAD];   // [k][m], tf32 bits
    __shared__ uint32_t Bs[GK][GN + PAD];   // [k][n], tf32 bits

    const int tid  = threadIdx.x;
    const int wid  = tid >> 5;
    const int lane = tid & 31;
    const int g    = lane >> 2;   // groupID 0..7
    const int tg   = lane & 3;    // thread-in-group 0..3

    const int brow = blockIdx.y * GM;
    const int bcol = blockIdx.x * GN;
    const int wm   = (wid & 1) * 64;    // warp row offset in tile
    const int wn   = (wid >> 1) * 32;   // warp col offset in tile

    // global->smem staging indices
    const int a_r = tid >> 3;          // 0..31 (row within 32-row chunk)
    const int a_c = (tid & 7) * 4;     // k col 0..28
    const int b_r = tid >> 6;          // 0..3 (k row within 4-row chunk)
    const int b_c = (tid & 63) * 2;    // n col 0..126

    float c[4][4][4];
    #pragma unroll
    for (int i = 0; i < 4; i++)
        #pragma unroll
        for (int j = 0; j < 4; j++)
            #pragma unroll
            for (int r = 0; r < 4; r++) c[i][j][r] = 0.f;

    for (int k0 = 0; k0 < K; k0 += GK) {
        // A tile: 128 rows x 32 k. Each thread: 4 float4 (transposed store).
        #pragma unroll
        for (int i = 0; i < 4; i++) {
            int r = a_r + 32 * i;
            float4 v = *(const float4*)&A[(size_t)(brow + r) * K + k0 + a_c];
            As[a_c + 0][r] = f2tf32(v.x);
            As[a_c + 1][r] = f2tf32(v.y);
            As[a_c + 2][r] = f2tf32(v.z);
            As[a_c + 3][r] = f2tf32(v.w);
        }
        // B tile: 32 k x 128 n. Each thread: 8 float2 rows b_r + 4*i.
        #pragma unroll
        for (int i = 0; i < 8; i++) {
            int r = b_r + 4 * i;
            float2 v = *(const float2*)&B[(size_t)(k0 + r) * N + bcol + b_c];
            Bs[r][b_c + 0] = f2tf32(v.x);
            Bs[r][b_c + 1] = f2tf32(v.y);
        }
        __syncthreads();

        #pragma unroll
        for (int kk = 0; kk < GK; kk += 8) {
            uint32_t af[4][4], bf[4][2];
            #pragma unroll
            for (int mf = 0; mf < 4; mf++) {
                int m = wm + 16 * mf;
                af[mf][0] = As[kk + tg    ][m + g    ];
                af[mf][1] = As[kk + tg    ][m + g + 8];
                af[mf][2] = As[kk + tg + 4][m + g    ];
                af[mf][3] = As[kk + tg + 4][m + g + 8];
            }
            #pragma unroll
            for (int nf = 0; nf < 4; nf++) {
                int n = wn + 8 * nf;
                bf[nf][0] = Bs[kk + tg    ][n + g];
                bf[nf][1] = Bs[kk + tg + 4][n + g];
            }
            #pragma unroll
            for (int mf = 0; mf < 4; mf++)
                #pragma unroll
                for (int nf = 0; nf < 4; nf++)
                    mma_tf32(c[mf][nf][0], c[mf][nf][1], c[mf][nf][2], c[mf][nf][3],
                             af[mf][0], af[mf][1], af[mf][2], af[mf][3],
                             bf[nf][0], bf[nf][1]);
        }
        __syncthreads();
    }

    // Epilogue: c0,c1 -> row g, cols 2tg,2tg+1 ; c2,c3 -> row g+8
    #pragma unroll
    for (int mf = 0; mf < 4; mf++) {
        int r0 = brow + wm + 16 * mf + g;
        #pragma unroll
        for (int nf = 0; nf < 4; nf++) {
            int cc = bcol + wn + 8 * nf + 2 * tg;
            *(float2*)&C[(size_t)r0 * N + cc]       = make_float2(c[mf][nf][0], c[mf][nf][1]);
            *(float2*)&C[(size_t)(r0 + 8) * N + cc] = make_float2(c[mf][nf][2], c[mf][nf][3]);
        }
    }
}

// ---------------------------------------------------------------------------
// Fused rmsnorm (over full row width) + RoPE (per 64-wide head).
// One block per sequence row, 256 threads. In-place.
// ---------------------------------------------------------------------------
__global__ __launch_bounds__(256) void rms_rope_kernel(
    float* __restrict__ buf, const float* __restrict__ w,
    const float* __restrict__ cosp, const float* __restrict__ sinp, int width)
{
    const int s = blockIdx.x;
    float* row = buf + (size_t)s * width;
    const int tid = threadIdx.x;

    float ss = 0.f;
    for (int i = tid; i < width; i += 256) {
        float v = row[i];
        ss += v * v;
    }
    #pragma unroll
    for (int o = 16; o; o >>= 1) ss += __shfl_xor_sync(0xffffffffu, ss, o);

    __shared__ float red[8];
    __shared__ float s_r;
    if ((tid & 31) == 0) red[tid >> 5] = ss;
    __syncthreads();
    if (tid == 0) {
        float t = 0.f;
        #pragma unroll
        for (int i = 0; i < 8; i++) t += red[i];
        s_r = rsqrtf(t / (float)width + EPS_);
    }
    __syncthreads();
    const float r = s_r;

    const float* cr = cosp + (size_t)s * HD_;
    const float* sr = sinp + (size_t)s * HD_;
    const int npairs = width >> 1;
    for (int p = tid; p < npairs; p += 256) {
        int head = p >> 5;            // 32 pairs per head
        int d    = p & 31;
        int i0 = head * HD_ + d;
        int i1 = i0 + 32;
        float v0 = row[i0] * r * w[i0];
        float v1 = row[i1] * r * w[i1];
        float c0 = cr[d],      s0 = sr[d];
        float c1 = cr[d + 32], s1 = sr[d + 32];
        row[i0] = v0 * c0 - v1 * s0;   // x1*cos - x2*sin
        row[i1] = v1 * c1 + v0 * s1;   // x2*cos + x1*sin
    }
}

// ---------------------------------------------------------------------------
// Flash attention, fp32, causal, GQA (4 q-heads per kv-head).
// grid = (S/64, H). 256 threads. 64x64 q/kv tiles, online softmax.
// ---------------------------------------------------------------------------
#define FA_BM 64
#define FA_BN 64

__global__ __launch_bounds__(256) void flash_kernel(
    const float* __restrict__ Q, const float* __restrict__ K,
    const float* __restrict__ V, float* __restrict__ O)
{
    __shared__ float Qst[HD_][FA_BM];     // [d][m]
    __shared__ float KP[FA_BN][FA_BM];    // K as [d][n]; reused as P [m][n]
    __shared__ float Vs[FA_BN][HD_];      // [n][d]

    const int tid = threadIdx.x;
    const int ty = tid >> 4;              // 0..15 -> 4 q rows
    const int tx = tid & 15;              // 0..15 -> 4 cols
    const int q0 = blockIdx.x * FA_BM;
    const int h  = blockIdx.y;
    const int kh = h >> 2;                // N_REP = 4

    // Load Q tile transposed: Qst[d][m]
    {
        int m  = tid >> 2;
        int d0 = (tid & 3) * 16;
        const float* qrow = Q + (size_t)(q0 + m) * D_ + h * HD_;
        #pragma unroll
        for (int i = 0; i < 4; i++) {
            float4 v = *(const float4*)(qrow + d0 + 4 * i);
            Qst[d0 + 4*i + 0][m] = v.x;
            Qst[d0 + 4*i + 1][m] = v.y;
            Qst[d0 + 4*i + 2][m] = v.z;
            Qst[d0 + 4*i + 3][m] = v.w;
        }
    }

    float acc[4][4] = {};
    float mrow[4], lrow[4];
    #pragma unroll
    for (int i = 0; i < 4; i++) { mrow[i] = -1e30f; lrow[i] = 0.f; }

    const float scale = 0.125f;           // HD^-0.5
    const int n_end = q0 + FA_BM;

    for (int n0 = 0; n0 < n_end; n0 += FA_BN) {
        // Load K tile transposed into KP[d][n]; V tile natural into Vs[n][d]
        {
            int n  = tid >> 2;
            int d0 = (tid & 3) * 16;
            const float* krow = K + (size_t)(n0 + n) * KD_ + kh * HD_;
            const float* vrow = V + (size_t)(n0 + n) * KD_ + kh * HD_;
            #pragma unroll
            for (int i = 0; i < 4; i++) {
                float4 kv = *(const float4*)(krow + d0 + 4 * i);
                KP[d0 + 4*i + 0][n] = kv.x;
                KP[d0 + 4*i + 1][n] = kv.y;
                KP[d0 + 4*i + 2][n] = kv.z;
                KP[d0 + 4*i + 3][n] = kv.w;
                *(float4*)&Vs[n][d0 + 4*i] = *(const float4*)(vrow + d0 + 4*i);
            }
        }
        __syncthreads();

        // S = Q K^T (64x64), microtile 4x4
        float sreg[4][4] = {};
        #pragma unroll
        for (int kk = 0; kk < HD_; kk++) {
            float ar[4], br[4];
            float4 av = *(const float4*)&Qst[kk][ty * 4];
            ar[0] = av.x; ar[1] = av.y; ar[2] = av.z; ar[3] = av.w;
            float4 bv = *(const float4*)&KP[kk][tx * 4];
            br[0] = bv.x; br[1] = bv.y; br[2] = bv.z; br[3] = bv.w;
            #pragma unroll
            for (int i = 0; i < 4; i++)
                #pragma unroll
                for (int j = 0; j < 4; j++)
                    sreg[i][j] += ar[i] * br[j];
        }

        // scale + causal mask
        const bool diag = (n0 + FA_BN > q0);
        #pragma unroll
        for (int i = 0; i < 4; i++) {
            int rowg = q0 + ty * 4 + i;
            #pragma unroll
            for (int j = 0; j < 4; j++) {
                int colg = n0 + tx * 4 + j;
                float vv = sreg[i][j] * scale;
                if (diag && colg > rowg) vv = -1e30f;
                sreg[i][j] = vv;
            }
        }

        // online softmax per q row
        #pragma unroll
        for (int i = 0; i < 4; i++) {
            float tmax = sreg[i][0];
            #pragma unroll
            for (int j = 1; j < 4; j++) tmax = fmaxf(tmax, sreg[i][j]);
            #pragma unroll
            for (int o = 8; o; o >>= 1)
                tmax = fmaxf(tmax, __shfl_xor_sync(0xffffffffu, tmax, o));
            float mnew = fmaxf(mrow[i], tmax);
            float corr = __expf(mrow[i] - mnew);
            float rsum = 0.f;
            #pragma unroll
            for (int j = 0; j < 4; j++) {
                float p = __expf(sreg[i][j] - mnew);
                sreg[i][j] = p;
                rsum += p;
            }
            #pragma unroll
            for (int o = 8; o; o >>= 1)
                rsum += __shfl_xor_sync(0xffffffffu, rsum, o);
            lrow[i] = lrow[i] * corr + rsum;
            mrow[i] = mnew;
            #pragma unroll
            for (int j = 0; j < 4; j++) acc[i][j] *= corr;
        }

        __syncthreads();   // everyone done reading KP as K-tile

        // Write P into KP as [m][n]
        #pragma unroll
        for (int i = 0; i < 4; i++)
            *(float4*)&KP[ty * 4 + i][tx * 4] =
                make_float4(sreg[i][0], sreg[i][1], sreg[i][2], sreg[i][3]);
        __syncthreads();

        // O += P @ V
        #pragma unroll
        for (int kk = 0; kk < FA_BN; kk++) {
            float ar[4], br[4];
            #pragma unroll
            for (int i = 0; i < 4; i++) ar[i] = KP[ty * 4 + i][kk];
            float4 bv = *(const float4*)&Vs[kk][tx * 4];
            br[0] = bv.x; br[1] = bv.y; br[2] = bv.z; br[3] = bv.w;
            #pragma unroll
            for (int i = 0; i < 4; i++)
                #pragma unroll
                for (int j = 0; j < 4; j++)
                    acc[i][j] += ar[i] * br[j];
        }
        __syncthreads();   // before next tile overwrites KP/Vs
    }

    // finalize: divide by l, write out (S, H*HD)
    #pragma unroll
    for (int i = 0; i < 4; i++) {
        int rowg = q0 + ty * 4 + i;
        float inv = 1.f / lrow[i];
        #pragma unroll
        for (int j = 0; j < 4; j++)
            O[(size_t)rowg * D_ + h * HD_ + tx * 4 + j] = acc[i][j] * inv;
    }
}

// ---------------------------------------------------------------------------
// Launch
// ---------------------------------------------------------------------------
extern "C" void kernel_launch(void* const* d_in, const int* in_sizes, int n_in,
                              void* d_out, int out_size)
{
    const float* x    = (const float*)d_in[0];
    const float* cosp = (const float*)d_in[1];
    const float* sinp = (const float*)d_in[2];
    // d_in[3] = mask (causal tril, recomputed analytically) — unused
    const float* Wq   = (const float*)d_in[4];
    const float* Wk   = (const float*)d_in[5];
    const float* Wv   = (const float*)d_in[6];
    const float* Wo   = (const float*)d_in[7];
    const float* qn_w = (const float*)d_in[8];
    const float* kn_w = (const float*)d_in[9];
    float* out = (float*)d_out;

    float *qp, *kp, *vp, *ap;
    cudaGetSymbolAddress((void**)&qp, g_q);
    cudaGetSymbolAddress((void**)&kp, g_k);
    cudaGetSymbolAddress((void**)&vp, g_v);
    cudaGetSymbolAddress((void**)&ap, g_att);

    // Projections (tf32 tensor cores)
    mma_gemm_kernel<<<dim3(D_ / GN, S_ / GM), 256>>>(x, Wq, qp, S_, D_, D_);
    mma_gemm_kernel<<<dim3(KD_ / GN, S_ / GM), 256>>>(x, Wk, kp, S_, KD_, D_);
    mma_gemm_kernel<<<dim3(KD_ / GN, S_ / GM), 256>>>(x, Wv, vp, S_, KD_, D_);

    // rmsnorm + RoPE (in place)
    rms_rope_kernel<<<S_, 256>>>(qp, qn_w, cosp, sinp, D_);
    rms_rope_kernel<<<S_, 256>>>(kp, kn_w, cosp, sinp, KD_);

    // Causal GQA flash attention (fp32)
    flash_kernel<<<dim3(S_ / FA_BM, H_), 256>>>(qp, kp, vp, ap);

    // Output projection (tf32 tensor cores)
    mma_gemm_kernel<<<dim3(D_ / GN, S_ / GM), 256>>>(ap, Wo, out, S_, D_, D_);
}

// round 8
// speedup vs baseline: 2.1266x; 1.3848x over previous
#include <cuda_runtime.h>
#include <cuda_bf16.h>
#include <cstdint>

// Problem constants
#define S_   2048
#define D_   2048
#define H_   32
#define KVH_ 8
#define HD_  64
#define KD_  512   // KVH*HD
#define EPS_ 1e-5f

// ---------------------------------------------------------------------------
// Scratch (no allocations allowed -> __device__ globals)
// ---------------------------------------------------------------------------
__device__ float g_q[S_ * D_];     // q after proj / rmsnorm+rope
__device__ float g_k[S_ * KD_];    // k after proj / rmsnorm+rope
__device__ float g_v[S_ * KD_];    // v
__device__ float g_att[S_ * D_];   // attention output (S, H*HD)

__device__ __forceinline__ uint32_t f2tf32(float x) {
    uint32_t r;
    asm("cvt.rna.tf32.f32 %0, %1;" : "=r"(r) : "f"(x));
    return r;
}

__device__ __forceinline__ void mma_tf32(
    float& c0, float& c1, float& c2, float& c3,
    uint32_t a0, uint32_t a1, uint32_t a2, uint32_t a3,
    uint32_t b0, uint32_t b1)
{
    asm volatile(
        "mma.sync.aligned.m16n8k8.row.col.f32.tf32.tf32.f32 "
        "{%0,%1,%2,%3}, {%4,%5,%6,%7}, {%8,%9}, {%0,%1,%2,%3};\n"
        : "+f"(c0), "+f"(c1), "+f"(c2), "+f"(c3)
        : "r"(a0), "r"(a1), "r"(a2), "r"(a3), "r"(b0), "r"(b1));
}

// ---------------------------------------------------------------------------
// TF32 tensor-core GEMM: C[M,N] = A[M,K] @ B[K,N], row-major fp32 in/out.
// 128x128 block tile, BK=32, 256 threads (8 warps, 2x4 grid, 64x32 warp tile).
// ---------------------------------------------------------------------------
#define GM 128
#define GN 128
#define GK 32
#define PAD 8   // row pad (words) -> fragment LDS hits 32 distinct banks

__global__ __launch_bounds__(256) void mma_gemm_kernel(
    const float* __restrict__ A, const float* __restrict__ B,
    float* __restrict__ C, int M, int N, int K)
{
    __shared__ uint32_t As[GK][GM + PAD];   // [k][m], tf32 bits
    __shared__ uint32_t Bs[GK][GN + PAD];   // [k][n], tf32 bits

    const int tid  = threadIdx.x;
    const int wid  = tid >> 5;
    const int lane = tid & 31;
    const int g    = lane >> 2;   // groupID 0..7
    const int tg   = lane & 3;    // thread-in-group 0..3

    const int brow = blockIdx.y * GM;
    const int bcol = blockIdx.x * GN;
    const int wm   = (wid & 1) * 64;    // warp row offset in tile
    const int wn   = (wid >> 1) * 32;   // warp col offset in tile

    const int a_r = tid >> 3;          // 0..31
    const int a_c = (tid & 7) * 4;     // 0,4,..28
    const int b_r = tid >> 6;          // 0..3
    const int b_c = (tid & 63) * 2;    // 0..126

    float c[4][4][4];
    #pragma unroll
    for (int i = 0; i < 4; i++)
        #pragma unroll
        for (int j = 0; j < 4; j++)
            #pragma unroll
            for (int r = 0; r < 4; r++) c[i][j][r] = 0.f;

    for (int k0 = 0; k0 < K; k0 += GK) {
        #pragma unroll
        for (int i = 0; i < 4; i++) {
            int r = a_r + 32 * i;
            float4 v = *(const float4*)&A[(size_t)(brow + r) * K + k0 + a_c];
            As[a_c + 0][r] = f2tf32(v.x);
            As[a_c + 1][r] = f2tf32(v.y);
            As[a_c + 2][r] = f2tf32(v.z);
            As[a_c + 3][r] = f2tf32(v.w);
        }
        #pragma unroll
        for (int i = 0; i < 8; i++) {
            int r = b_r + 4 * i;
            float2 v = *(const float2*)&B[(size_t)(k0 + r) * N + bcol + b_c];
            Bs[r][b_c + 0] = f2tf32(v.x);
            Bs[r][b_c + 1] = f2tf32(v.y);
        }
        __syncthreads();

        #pragma unroll
        for (int kk = 0; kk < GK; kk += 8) {
            uint32_t af[4][4], bf[4][2];
            #pragma unroll
            for (int mf = 0; mf < 4; mf++) {
                int m = wm + 16 * mf;
                af[mf][0] = As[kk + tg    ][m + g    ];
                af[mf][1] = As[kk + tg    ][m + g + 8];
                af[mf][2] = As[kk + tg + 4][m + g    ];
                af[mf][3] = As[kk + tg + 4][m + g + 8];
            }
            #pragma unroll
            for (int nf = 0; nf < 4; nf++) {
                int n = wn + 8 * nf;
                bf[nf][0] = Bs[kk + tg    ][n + g];
                bf[nf][1] = Bs[kk + tg + 4][n + g];
            }
            #pragma unroll
            for (int mf = 0; mf < 4; mf++)
                #pragma unroll
                for (int nf = 0; nf < 4; nf++)
                    mma_tf32(c[mf][nf][0], c[mf][nf][1], c[mf][nf][2], c[mf][nf][3],
                             af[mf][0], af[mf][1], af[mf][2], af[mf][3],
                             bf[nf][0], bf[nf][1]);
        }
        __syncthreads();
    }

    #pragma unroll
    for (int mf = 0; mf < 4; mf++) {
        int r0 = brow + wm + 16 * mf + g;
        #pragma unroll
        for (int nf = 0; nf < 4; nf++) {
            int cc = bcol + wn + 8 * nf + 2 * tg;
            *(float2*)&C[(size_t)r0 * N + cc]       = make_float2(c[mf][nf][0], c[mf][nf][1]);
            *(float2*)&C[(size_t)(r0 + 8) * N + cc] = make_float2(c[mf][nf][2], c[mf][nf][3]);
        }
    }
}

// ---------------------------------------------------------------------------
// Fused rmsnorm + RoPE. One block per sequence row, 256 threads. In-place.
// ---------------------------------------------------------------------------
__global__ __launch_bounds__(256) void rms_rope_kernel(
    float* __restrict__ buf, const float* __restrict__ w,
    const float* __restrict__ cosp, const float* __restrict__ sinp, int width)
{
    const int s = blockIdx.x;
    float* row = buf + (size_t)s * width;
    const int tid = threadIdx.x;

    float ss = 0.f;
    for (int i = tid; i < width; i += 256) {
        float v = row[i];
        ss += v * v;
    }
    #pragma unroll
    for (int o = 16; o; o >>= 1) ss += __shfl_xor_sync(0xffffffffu, ss, o);

    __shared__ float red[8];
    __shared__ float s_r;
    if ((tid & 31) == 0) red[tid >> 5] = ss;
    __syncthreads();
    if (tid == 0) {
        float t = 0.f;
        #pragma unroll
        for (int i = 0; i < 8; i++) t += red[i];
        s_r = rsqrtf(t / (float)width + EPS_);
    }
    __syncthreads();
    const float r = s_r;

    const float* cr = cosp + (size_t)s * HD_;
    const float* sr = sinp + (size_t)s * HD_;
    const int npairs = width >> 1;
    for (int p = tid; p < npairs; p += 256) {
        int head = p >> 5;
        int d    = p & 31;
        int i0 = head * HD_ + d;
        int i1 = i0 + 32;
        float v0 = row[i0] * r * w[i0];
        float v1 = row[i1] * r * w[i1];
        float c0 = cr[d],      s0 = sr[d];
        float c1 = cr[d + 32], s1 = sr[d + 32];
        row[i0] = v0 * c0 - v1 * s0;
        row[i1] = v1 * c1 + v0 * s1;
    }
}

// ---------------------------------------------------------------------------
// Flash attention with tf32 mma.sync, causal, GQA (4 q-heads per kv-head).
// grid = (S/64, H), 128 threads (4 warps). Each warp: 16 q rows x 64 kv cols.
// Q held in registers as A-fragments (pre-scaled). K staged [d][n] stride 72
// (conflict-free B-frags), P written to smem union over K at stride 68
// (conflict-free A-frags), V [n][d] stride 72.
// ---------------------------------------------------------------------------
#define FW 72   // K/V smem row stride (72 % 32 == 8 -> conflict-free b-frags)
#define PW 68   // P smem row stride  (68 % 32 == 4 -> conflict-free a-frags)

__global__ __launch_bounds__(128) void flash_mma_kernel(
    const float* __restrict__ Q, const float* __restrict__ K,
    const float* __restrict__ V, float* __restrict__ O)
{
    __shared__ uint32_t KP[64 * FW];   // union: K tile [d][n] / P tile [m][k]
    __shared__ uint32_t Vs[64 * FW];   // V tile [kv][d]

    const int tid  = threadIdx.x;
    const int wid  = tid >> 5;         // 0..3
    const int lane = tid & 31;
    const int g    = lane >> 2;        // 0..7
    const int tg   = lane & 3;         // 0..3
    const int wr   = wid * 16;         // warp's q-row offset in tile

    const int q0 = blockIdx.x * 64;
    const int h  = blockIdx.y;
    const int kh = h >> 2;             // N_REP = 4

    // --- Q A-fragments in registers, pre-scaled by HD^-0.5 ---
    uint32_t qf[8][4];
    {
        const float* q_r0 = Q + (size_t)(q0 + wr + g)     * D_ + h * HD_;
        const float* q_r1 = Q + (size_t)(q0 + wr + g + 8) * D_ + h * HD_;
        #pragma unroll
        for (int ks = 0; ks < 8; ks++) {
            qf[ks][0] = f2tf32(q_r0[8 * ks + tg]     * 0.125f);
            qf[ks][1] = f2tf32(q_r1[8 * ks + tg]     * 0.125f);
            qf[ks][2] = f2tf32(q_r0[8 * ks + tg + 4] * 0.125f);
            qf[ks][3] = f2tf32(q_r1[8 * ks + tg + 4] * 0.125f);
        }
    }

    float of[8][4];
    #pragma unroll
    for (int nf = 0; nf < 8; nf++)
        #pragma unroll
        for (int r = 0; r < 4; r++) of[nf][r] = 0.f;
    float m0 = -1e30f, m1 = -1e30f, l0 = 0.f, l1 = 0.f;

    // K/V staging indices: 2 threads per kv row, 32 d each
    const int ld_n  = tid >> 1;
    const int ld_d0 = (tid & 1) * 32;

    for (int n0 = 0; n0 <= q0; n0 += 64) {
        // ---- stage K (transposed, tf32) and V (natural, tf32) ----
        {
            const float* krow = K + (size_t)(n0 + ld_n) * KD_ + kh * HD_ + ld_d0;
            const float* vrow = V + (size_t)(n0 + ld_n) * KD_ + kh * HD_ + ld_d0;
            #pragma unroll
            for (int i = 0; i < 8; i++) {
                float4 kv4 = *(const float4*)(krow + 4 * i);
                KP[(ld_d0 + 4*i + 0) * FW + ld_n] = f2tf32(kv4.x);
                KP[(ld_d0 + 4*i + 1) * FW + ld_n] = f2tf32(kv4.y);
                KP[(ld_d0 + 4*i + 2) * FW + ld_n] = f2tf32(kv4.z);
                KP[(ld_d0 + 4*i + 3) * FW + ld_n] = f2tf32(kv4.w);
                float4 vv4 = *(const float4*)(vrow + 4 * i);
                uint4 vb = make_uint4(f2tf32(vv4.x), f2tf32(vv4.y),
                                      f2tf32(vv4.z), f2tf32(vv4.w));
                *(uint4*)&Vs[ld_n * FW + ld_d0 + 4 * i] = vb;
            }
        }
        __syncthreads();

        // ---- S = Q K^T (16x64 per warp) ----
        float sf[8][4];
        #pragma unroll
        for (int nf = 0; nf < 8; nf++)
            #pragma unroll
            for (int r = 0; r < 4; r++) sf[nf][r] = 0.f;

        #pragma unroll
        for (int ks = 0; ks < 8; ks++) {
            #pragma unroll
            for (int nf = 0; nf < 8; nf++) {
                uint32_t b0 = KP[(8 * ks + tg)     * FW + 8 * nf + g];
                uint32_t b1 = KP[(8 * ks + tg + 4) * FW + 8 * nf + g];
                mma_tf32(sf[nf][0], sf[nf][1], sf[nf][2], sf[nf][3],
                         qf[ks][0], qf[ks][1], qf[ks][2], qf[ks][3], b0, b1);
            }
        }

        // ---- causal mask (diagonal tile only) ----
        if (n0 == q0) {
            #pragma unroll
            for (int nf = 0; nf < 8; nf++) {
                int c = 8 * nf + 2 * tg;
                if (c     > wr + g)     sf[nf][0] = -1e30f;
                if (c + 1 > wr + g)     sf[nf][1] = -1e30f;
                if (c     > wr + g + 8) sf[nf][2] = -1e30f;
                if (c + 1 > wr + g + 8) sf[nf][3] = -1e30f;
            }
        }

        // ---- online softmax (rows g and g+8; reduce over 4 tg lanes) ----
        {
            float tm0 = -1e30f, tm1 = -1e30f;
            #pragma unroll
            for (int nf = 0; nf < 8; nf++) {
                tm0 = fmaxf(tm0, fmaxf(sf[nf][0], sf[nf][1]));
                tm1 = fmaxf(tm1, fmaxf(sf[nf][2], sf[nf][3]));
            }
            #pragma unroll
            for (int o = 1; o <= 2; o <<= 1) {
                tm0 = fmaxf(tm0, __shfl_xor_sync(0xffffffffu, tm0, o));
                tm1 = fmaxf(tm1, __shfl_xor_sync(0xffffffffu, tm1, o));
            }
            float mn0 = fmaxf(m0, tm0);
            float mn1 = fmaxf(m1, tm1);
            float cor0 = __expf(m0 - mn0);
            float cor1 = __expf(m1 - mn1);
            float rs0 = 0.f, rs1 = 0.f;
            #pragma unroll
            for (int nf = 0; nf < 8; nf++) {
                float p0 = __expf(sf[nf][0] - mn0);
                float p1 = __expf(sf[nf][1] - mn0);
                float p2 = __expf(sf[nf][2] - mn1);
                float p3 = __expf(sf[nf][3] - mn1);
                sf[nf][0] = p0; sf[nf][1] = p1; sf[nf][2] = p2; sf[nf][3] = p3;
                rs0 += p0 + p1; rs1 += p2 + p3;
            }
            #pragma unroll
            for (int o = 1; o <= 2; o <<= 1) {
                rs0 += __shfl_xor_sync(0xffffffffu, rs0, o);
                rs1 += __shfl_xor_sync(0xffffffffu, rs1, o);
            }
            l0 = l0 * cor0 + rs0;  m0 = mn0;
            l1 = l1 * cor1 + rs1;  m1 = mn1;
            #pragma unroll
            for (int nf = 0; nf < 8; nf++) {
                of[nf][0] *= cor0; of[nf][1] *= cor0;
                of[nf][2] *= cor1; of[nf][3] *= cor1;
            }
        }

        __syncthreads();   // all warps done reading K tile from KP

        // ---- write P (tf32) into warp-private rows of KP union ----
        {
            uint32_t* Ps = KP + wr * PW;
            #pragma unroll
            for (int nf = 0; nf < 8; nf++) {
                int c = 8 * nf + 2 * tg;
                Ps[g * PW + c]           = f2tf32(sf[nf][0]);
                Ps[g * PW + c + 1]       = f2tf32(sf[nf][1]);
                Ps[(g + 8) * PW + c]     = f2tf32(sf[nf][2]);
                Ps[(g + 8) * PW + c + 1] = f2tf32(sf[nf][3]);
            }
        }
        __syncwarp();

        // ---- O += P @ V ----
        {
            const uint32_t* Ps = KP + wr * PW;
            #pragma unroll
            for (int ks = 0; ks < 8; ks++) {
                uint32_t a0 = Ps[g * PW + 8 * ks + tg];
                uint32_t a1 = Ps[(g + 8) * PW + 8 * ks + tg];
                uint32_t a2 = Ps[g * PW + 8 * ks + tg + 4];
                uint32_t a3 = Ps[(g + 8) * PW + 8 * ks + tg + 4];
                #pragma unroll
                for (int nf = 0; nf < 8; nf++) {
                    uint32_t b0 = Vs[(8 * ks + tg)     * FW + 8 * nf + g];
                    uint32_t b1 = Vs[(8 * ks + tg + 4) * FW + 8 * nf + g];
                    mma_tf32(of[nf][0], of[nf][1], of[nf][2], of[nf][3],
                             a0, a1, a2, a3, b0, b1);
                }
            }
        }
        __syncthreads();   // before next tile overwrites KP / Vs
    }

    // ---- finalize ----
    {
        float inv0 = 1.f / l0;
        float inv1 = 1.f / l1;
        float* o_r0 = O + (size_t)(q0 + wr + g)     * D_ + h * HD_;
        float* o_r1 = O + (size_t)(q0 + wr + g + 8) * D_ + h * HD_;
        #pragma unroll
        for (int nf = 0; nf < 8; nf++) {
            int c = 8 * nf + 2 * tg;
            *(float2*)&o_r0[c] = make_float2(of[nf][0] * inv0, of[nf][1] * inv0);
            *(float2*)&o_r1[c] = make_float2(of[nf][2] * inv1, of[nf][3] * inv1);
        }
    }
}

// ---------------------------------------------------------------------------
// Launch
// ---------------------------------------------------------------------------
extern "C" void kernel_launch(void* const* d_in, const int* in_sizes, int n_in,
                              void* d_out, int out_size)
{
    const float* x    = (const float*)d_in[0];
    const float* cosp = (const float*)d_in[1];
    const float* sinp = (const float*)d_in[2];
    // d_in[3] = mask (causal tril, recomputed analytically) — unused
    const float* Wq   = (const float*)d_in[4];
    const float* Wk   = (const float*)d_in[5];
    const float* Wv   = (const float*)d_in[6];
    const float* Wo   = (const float*)d_in[7];
    const float* qn_w = (const float*)d_in[8];
    const float* kn_w = (const float*)d_in[9];
    float* out = (float*)d_out;

    float *qp, *kp, *vp, *ap;
    cudaGetSymbolAddress((void**)&qp, g_q);
    cudaGetSymbolAddress((void**)&kp, g_k);
    cudaGetSymbolAddress((void**)&vp, g_v);
    cudaGetSymbolAddress((void**)&ap, g_att);

    // Projections (tf32 tensor cores)
    mma_gemm_kernel<<<dim3(D_ / GN, S_ / GM), 256>>>(x, Wq, qp, S_, D_, D_);
    mma_gemm_kernel<<<dim3(KD_ / GN, S_ / GM), 256>>>(x, Wk, kp, S_, KD_, D_);
    mma_gemm_kernel<<<dim3(KD_ / GN, S_ / GM), 256>>>(x, Wv, vp, S_, KD_, D_);

    // rmsnorm + RoPE (in place)
    rms_rope_kernel<<<S_, 256>>>(qp, qn_w, cosp, sinp, D_);
    rms_rope_kernel<<<S_, 256>>>(kp, kn_w, cosp, sinp, KD_);

    // Causal GQA flash attention (tf32 tensor cores)
    flash_mma_kernel<<<dim3(S_ / 64, H_), 128>>>(qp, kp, vp, ap);

    // Output projection (tf32 tensor cores)
    mma_gemm_kernel<<<dim3(D_ / GN, S_ / GM), 256>>>(ap, Wo, out, S_, D_, D_);
}

// round 9
// speedup vs baseline: 2.8352x; 1.3332x over previous
#include <cuda_runtime.h>
#include <cuda_fp16.h>
#include <cuda_bf16.h>
#include <cstdint>

// Problem constants
#define S_   2048
#define D_   2048
#define H_   32
#define KVH_ 8
#define HD_  64
#define KD_  512    // KVH*HD
#define QKVW 3072   // packed qkv row width: q[0,2048) k[2048,2560) v[2560,3072)
#define EPS_ 1e-5f

// ---------------------------------------------------------------------------
// Scratch (no allocations allowed -> __device__ globals)
// ---------------------------------------------------------------------------
__device__ float g_qkv[S_ * QKVW];  // packed q|k|v after proj (later norm+rope)
__device__ float g_att[S_ * D_];    // attention output (S, H*HD)

// ---------------------------------------------------------------------------
// Helpers
// ---------------------------------------------------------------------------
__device__ __forceinline__ uint32_t pack_h2(float lo, float hi) {
    __half2 h = __floats2half2_rn(lo, hi);
    return *reinterpret_cast<uint32_t*>(&h);
}

__device__ __forceinline__ uint32_t f2tf32(float x) {
    uint32_t r;
    asm("cvt.rna.tf32.f32 %0, %1;" : "=r"(r) : "f"(x));
    return r;
}

__device__ __forceinline__ void mma_f16(
    float& c0, float& c1, float& c2, float& c3,
    uint32_t a0, uint32_t a1, uint32_t a2, uint32_t a3,
    uint32_t b0, uint32_t b1)
{
    asm volatile(
        "mma.sync.aligned.m16n8k16.row.col.f32.f16.f16.f32 "
        "{%0,%1,%2,%3}, {%4,%5,%6,%7}, {%8,%9}, {%0,%1,%2,%3};\n"
        : "+f"(c0), "+f"(c1), "+f"(c2), "+f"(c3)
        : "r"(a0), "r"(a1), "r"(a2), "r"(a3), "r"(b0), "r"(b1));
}

__device__ __forceinline__ void mma_tf32(
    float& c0, float& c1, float& c2, float& c3,
    uint32_t a0, uint32_t a1, uint32_t a2, uint32_t a3,
    uint32_t b0, uint32_t b1)
{
    asm volatile(
        "mma.sync.aligned.m16n8k8.row.col.f32.tf32.tf32.f32 "
        "{%0,%1,%2,%3}, {%4,%5,%6,%7}, {%8,%9}, {%0,%1,%2,%3};\n"
        : "+f"(c0), "+f"(c1), "+f"(c2), "+f"(c3)
        : "r"(a0), "r"(a1), "r"(a2), "r"(a3), "r"(b0), "r"(b1));
}

__device__ __forceinline__ void ldsm_x4(
    uint32_t& r0, uint32_t& r1, uint32_t& r2, uint32_t& r3, uint32_t addr)
{
    asm volatile("ldmatrix.sync.aligned.m8n8.x4.shared.b16 {%0,%1,%2,%3}, [%4];\n"
                 : "=r"(r0), "=r"(r1), "=r"(r2), "=r"(r3) : "r"(addr));
}

__device__ __forceinline__ void ldsm_x4_t(
    uint32_t& r0, uint32_t& r1, uint32_t& r2, uint32_t& r3, uint32_t addr)
{
    asm volatile("ldmatrix.sync.aligned.m8n8.x4.trans.shared.b16 {%0,%1,%2,%3}, [%4];\n"
                 : "=r"(r0), "=r"(r1), "=r"(r2), "=r"(r3) : "r"(addr));
}

// ---------------------------------------------------------------------------
// FP16 tensor-core GEMM core: C[128 rows][128 cols] tile of A[M,K]@B[K,N].
// GK=32, 256 threads (8 warps 2x4, warp tile 64x32), m16n8k16, f32 accum.
// A staged [m][k] (stride 40 halves), B staged [k][n] (stride 136 halves);
// fragments via ldmatrix(.trans) — both strides conflict-free for LDSM.
// ---------------------------------------------------------------------------
#define GK  32
#define AST 40    // As row stride in halves (80B: 16B-unit pattern distinct)
#define BST 136   // Bs row stride in halves (272B: k*17 mod 8 distinct)

__device__ __forceinline__ void hgemm_core(
    const float* __restrict__ A, int lda,
    const float* __restrict__ B, int ldb,
    float* __restrict__ C, int ldc,
    int K, int brow, int bcol, int ccol)
{
    __shared__ __half As[128 * AST];
    __shared__ __half Bs[GK * BST];

    const int tid  = threadIdx.x;
    const int wid  = tid >> 5;
    const int lane = tid & 31;
    const int g    = lane >> 2;
    const int tg   = lane & 3;
    const int wm   = (wid & 1) * 64;
    const int wn   = (wid >> 1) * 32;

    // staging indices
    const int a_m  = tid >> 1;          // 0..127
    const int a_k0 = (tid & 1) * 16;    // 0 or 16
    const int b_k  = tid >> 3;          // 0..31
    const int b_n0 = (tid & 7) * 16;    // 0..112

    // ldmatrix lane addressing
    const int l15 = lane & 15;
    const int lhi = lane >> 4;          // 0 or 1

    float c[4][4][4];
    #pragma unroll
    for (int i = 0; i < 4; i++)
        #pragma unroll
        for (int j = 0; j < 4; j++)
            #pragma unroll
            for (int r = 0; r < 4; r++) c[i][j][r] = 0.f;

    for (int k0 = 0; k0 < K; k0 += GK) {
        // ---- stage A [m][k] ----
        #pragma unroll
        for (int j = 0; j < 4; j++) {
            float4 v = *(const float4*)&A[(size_t)(brow + a_m) * lda + k0 + a_k0 + 4 * j];
            uint2 h = make_uint2(pack_h2(v.x, v.y), pack_h2(v.z, v.w));
            *(uint2*)&As[a_m * AST + a_k0 + 4 * j] = h;
        }
        // ---- stage B [k][n] ----
        #pragma unroll
        for (int j = 0; j < 4; j++) {
            float4 v = *(const float4*)&B[(size_t)(k0 + b_k) * ldb + bcol + b_n0 + 4 * j];
            uint2 h = make_uint2(pack_h2(v.x, v.y), pack_h2(v.z, v.w));
            *(uint2*)&Bs[b_k * BST + b_n0 + 4 * j] = h;
        }
        __syncthreads();

        #pragma unroll
        for (int ks = 0; ks < 2; ks++) {         // k-steps of 16
            uint32_t af[4][4];
            #pragma unroll
            for (int mf = 0; mf < 4; mf++) {
                const __half* p = &As[(wm + mf * 16 + l15) * AST + ks * 16 + lhi * 8];
                ldsm_x4(af[mf][0], af[mf][1], af[mf][2], af[mf][3],
                        (uint32_t)__cvta_generic_to_shared(p));
            }
            uint32_t bf[2][4];
            #pragma unroll
            for (int nb = 0; nb < 2; nb++) {
                const __half* p = &Bs[(ks * 16 + l15) * BST + wn + nb * 16 + lhi * 8];
                ldsm_x4_t(bf[nb][0], bf[nb][1], bf[nb][2], bf[nb][3],
                          (uint32_t)__cvta_generic_to_shared(p));
            }
            #pragma unroll
            for (int mf = 0; mf < 4; mf++)
                #pragma unroll
                for (int nf = 0; nf < 4; nf++) {
                    int nb = nf >> 1, hi = (nf & 1) * 2;
                    mma_f16(c[mf][nf][0], c[mf][nf][1], c[mf][nf][2], c[mf][nf][3],
                            af[mf][0], af[mf][1], af[mf][2], af[mf][3],
                            bf[nb][hi], bf[nb][hi + 1]);
                }
        }
        __syncthreads();
    }

    #pragma unroll
    for (int mf = 0; mf < 4; mf++) {
        int r0 = brow + wm + 16 * mf + g;
        #pragma unroll
        for (int nf = 0; nf < 4; nf++) {
            int cc = ccol + wn + 8 * nf + 2 * tg;
            *(float2*)&C[(size_t)r0 * ldc + cc]       = make_float2(c[mf][nf][0], c[mf][nf][1]);
            *(float2*)&C[(size_t)(r0 + 8) * ldc + cc] = make_float2(c[mf][nf][2], c[mf][nf][3]);
        }
    }
}

// Fused QKV projection: grid (24, 16). Col tiles 0-15 -> Wq, 16-19 -> Wk,
// 20-23 -> Wv; output packed into g_qkv [S][3072].
__global__ __launch_bounds__(256, 2) void qkv_gemm_kernel(
    const float* __restrict__ x,
    const float* __restrict__ Wq, const float* __restrict__ Wk,
    const float* __restrict__ Wv, float* __restrict__ qkv)
{
    const int bx = blockIdx.x;
    const float* B; int ldb, bcol;
    if (bx < 16)      { B = Wq; ldb = D_;  bcol = bx * 128; }
    else if (bx < 20) { B = Wk; ldb = KD_; bcol = (bx - 16) * 128; }
    else              { B = Wv; ldb = KD_; bcol = (bx - 20) * 128; }
    hgemm_core(x, D_, B, ldb, qkv, QKVW, D_, blockIdx.y * 128, bcol, bx * 128);
}

// Output projection: grid (16, 16).
__global__ __launch_bounds__(256, 2) void wo_gemm_kernel(
    const float* __restrict__ A, const float* __restrict__ Wo,
    float* __restrict__ C)
{
    hgemm_core(A, D_, Wo, D_, C, D_, D_,
               blockIdx.y * 128, blockIdx.x * 128, blockIdx.x * 128);
}

// ---------------------------------------------------------------------------
// Fused rmsnorm + RoPE over a [width]-wide slice of a strided row buffer.
// One block per sequence row, 256 threads. In-place.
// ---------------------------------------------------------------------------
__global__ __launch_bounds__(256) void rms_rope_kernel(
    float* __restrict__ base, int stride, int width,
    const float* __restrict__ w,
    const float* __restrict__ cosp, const float* __restrict__ sinp)
{
    const int s = blockIdx.x;
    float* row = base + (size_t)s * stride;
    const int tid = threadIdx.x;

    float ss = 0.f;
    for (int i = tid; i < width; i += 256) {
        float v = row[i];
        ss += v * v;
    }
    #pragma unroll
    for (int o = 16; o; o >>= 1) ss += __shfl_xor_sync(0xffffffffu, ss, o);

    __shared__ float red[8];
    __shared__ float s_r;
    if ((tid & 31) == 0) red[tid >> 5] = ss;
    __syncthreads();
    if (tid == 0) {
        float t = 0.f;
        #pragma unroll
        for (int i = 0; i < 8; i++) t += red[i];
        s_r = rsqrtf(t / (float)width + EPS_);
    }
    __syncthreads();
    const float r = s_r;

    const float* cr = cosp + (size_t)s * HD_;
    const float* sr = sinp + (size_t)s * HD_;
    const int npairs = width >> 1;
    for (int p = tid; p < npairs; p += 256) {
        int head = p >> 5;
        int d    = p & 31;
        int i0 = head * HD_ + d;
        int i1 = i0 + 32;
        float v0 = row[i0] * r * w[i0];
        float v1 = row[i1] * r * w[i1];
        float c0 = cr[d],      s0 = sr[d];
        float c1 = cr[d + 32], s1 = sr[d + 32];
        row[i0] = v0 * c0 - v1 * s0;
        row[i1] = v1 * c1 + v0 * s1;
    }
}

// ---------------------------------------------------------------------------
// Flash attention with tf32 mma.sync, causal, GQA (4 q-heads per kv-head).
// grid = (S/64, H), 128 threads (4 warps). Reads packed qkv (stride 3072).
// ---------------------------------------------------------------------------
#define FW 72   // K/V smem row stride (72 % 32 == 8 -> conflict-free b-frags)
#define PW 68   // P smem row stride  (68 % 32 == 4 -> conflict-free a-frags)

__global__ __launch_bounds__(128) void flash_mma_kernel(
    const float* __restrict__ Q, const float* __restrict__ K,
    const float* __restrict__ V, float* __restrict__ O)
{
    __shared__ uint32_t KP[64 * FW];   // union: K tile [d][n] / P tile [m][k]
    __shared__ uint32_t Vs[64 * FW];   // V tile [kv][d]

    const int tid  = threadIdx.x;
    const int wid  = tid >> 5;
    const int lane = tid & 31;
    const int g    = lane >> 2;
    const int tg   = lane & 3;
    const int wr   = wid * 16;

    const int q0 = blockIdx.x * 64;
    const int h  = blockIdx.y;
    const int kh = h >> 2;

    // --- Q A-fragments in registers, pre-scaled by HD^-0.5 ---
    uint32_t qf[8][4];
    {
        const float* q_r0 = Q + (size_t)(q0 + wr + g)     * QKVW + h * HD_;
        const float* q_r1 = Q + (size_t)(q0 + wr + g + 8) * QKVW + h * HD_;
        #pragma unroll
        for (int ks = 0; ks < 8; ks++) {
            qf[ks][0] = f2tf32(q_r0[8 * ks + tg]     * 0.125f);
            qf[ks][1] = f2tf32(q_r1[8 * ks + tg]     * 0.125f);
            qf[ks][2] = f2tf32(q_r0[8 * ks + tg + 4] * 0.125f);
            qf[ks][3] = f2tf32(q_r1[8 * ks + tg + 4] * 0.125f);
        }
    }

    float of[8][4];
    #pragma unroll
    for (int nf = 0; nf < 8; nf++)
        #pragma unroll
        for (int r = 0; r < 4; r++) of[nf][r] = 0.f;
    float m0 = -1e30f, m1 = -1e30f, l0 = 0.f, l1 = 0.f;

    const int ld_n  = tid >> 1;
    const int ld_d0 = (tid & 1) * 32;

    for (int n0 = 0; n0 <= q0; n0 += 64) {
        {
            const float* krow = K + (size_t)(n0 + ld_n) * QKVW + kh * HD_ + ld_d0;
            const float* vrow = V + (size_t)(n0 + ld_n) * QKVW + kh * HD_ + ld_d0;
            #pragma unroll
            for (int i = 0; i < 8; i++) {
                float4 kv4 = *(const float4*)(krow + 4 * i);
                KP[(ld_d0 + 4*i + 0) * FW + ld_n] = f2tf32(kv4.x);
                KP[(ld_d0 + 4*i + 1) * FW + ld_n] = f2tf32(kv4.y);
                KP[(ld_d0 + 4*i + 2) * FW + ld_n] = f2tf32(kv4.z);
                KP[(ld_d0 + 4*i + 3) * FW + ld_n] = f2tf32(kv4.w);
                float4 vv4 = *(const float4*)(vrow + 4 * i);
                uint4 vb = make_uint4(f2tf32(vv4.x), f2tf32(vv4.y),
                                      f2tf32(vv4.z), f2tf32(vv4.w));
                *(uint4*)&Vs[ld_n * FW + ld_d0 + 4 * i] = vb;
            }
        }
        __syncthreads();

        float sf[8][4];
        #pragma unroll
        for (int nf = 0; nf < 8; nf++)
            #pragma unroll
            for (int r = 0; r < 4; r++) sf[nf][r] = 0.f;

        #pragma unroll
        for (int ks = 0; ks < 8; ks++) {
            #pragma unroll
            for (int nf = 0; nf < 8; nf++) {
                uint32_t b0 = KP[(8 * ks + tg)     * FW + 8 * nf + g];
                uint32_t b1 = KP[(8 * ks + tg + 4) * FW + 8 * nf + g];
                mma_tf32(sf[nf][0], sf[nf][1], sf[nf][2], sf[nf][3],
                         qf[ks][0], qf[ks][1], qf[ks][2], qf[ks][3], b0, b1);
            }
        }

        if (n0 == q0) {
            #pragma unroll
            for (int nf = 0; nf < 8; nf++) {
                int c = 8 * nf + 2 * tg;
                if (c     > wr + g)     sf[nf][0] = -1e30f;
                if (c + 1 > wr + g)     sf[nf][1] = -1e30f;
                if (c     > wr + g + 8) sf[nf][2] = -1e30f;
                if (c + 1 > wr + g + 8) sf[nf][3] = -1e30f;
            }
        }

        {
            float tm0 = -1e30f, tm1 = -1e30f;
            #pragma unroll
            for (int nf = 0; nf < 8; nf++) {
                tm0 = fmaxf(tm0, fmaxf(sf[nf][0], sf[nf][1]));
                tm1 = fmaxf(tm1, fmaxf(sf[nf][2], sf[nf][3]));
            }
            #pragma unroll
            for (int o = 1; o <= 2; o <<= 1) {
                tm0 = fmaxf(tm0, __shfl_xor_sync(0xffffffffu, tm0, o));
                tm1 = fmaxf(tm1, __shfl_xor_sync(0xffffffffu, tm1, o));
            }
            float mn0 = fmaxf(m0, tm0);
            float mn1 = fmaxf(m1, tm1);
            float cor0 = __expf(m0 - mn0);
            float cor1 = __expf(m1 - mn1);
            float rs0 = 0.f, rs1 = 0.f;
            #pragma unroll
            for (int nf = 0; nf < 8; nf++) {
                float p0 = __expf(sf[nf][0] - mn0);
                float p1 = __expf(sf[nf][1] - mn0);
                float p2 = __expf(sf[nf][2] - mn1);
                float p3 = __expf(sf[nf][3] - mn1);
                sf[nf][0] = p0; sf[nf][1] = p1; sf[nf][2] = p2; sf[nf][3] = p3;
                rs0 += p0 + p1; rs1 += p2 + p3;
            }
            #pragma unroll
            for (int o = 1; o <= 2; o <<= 1) {
                rs0 += __shfl_xor_sync(0xffffffffu, rs0, o);
                rs1 += __shfl_xor_sync(0xffffffffu, rs1, o);
            }
            l0 = l0 * cor0 + rs0;  m0 = mn0;
            l1 = l1 * cor1 + rs1;  m1 = mn1;
            #pragma unroll
            for (int nf = 0; nf < 8; nf++) {
                of[nf][0] *= cor0; of[nf][1] *= cor0;
                of[nf][2] *= cor1; of[nf][3] *= cor1;
            }
        }

        __syncthreads();

        {
            uint32_t* Ps = KP + wr * PW;
            #pragma unroll
            for (int nf = 0; nf < 8; nf++) {
                int c = 8 * nf + 2 * tg;
                Ps[g * PW + c]           = f2tf32(sf[nf][0]);
                Ps[g * PW + c + 1]       = f2tf32(sf[nf][1]);
                Ps[(g + 8) * PW + c]     = f2tf32(sf[nf][2]);
                Ps[(g + 8) * PW + c + 1] = f2tf32(sf[nf][3]);
            }
        }
        __syncwarp();

        {
            const uint32_t* Ps = KP + wr * PW;
            #pragma unroll
            for (int ks = 0; ks < 8; ks++) {
                uint32_t a0 = Ps[g * PW + 8 * ks + tg];
                uint32_t a1 = Ps[(g + 8) * PW + 8 * ks + tg];
                uint32_t a2 = Ps[g * PW + 8 * ks + tg + 4];
                uint32_t a3 = Ps[(g + 8) * PW + 8 * ks + tg + 4];
                #pragma unroll
                for (int nf = 0; nf < 8; nf++) {
                    uint32_t b0 = Vs[(8 * ks + tg)     * FW + 8 * nf + g];
                    uint32_t b1 = Vs[(8 * ks + tg + 4) * FW + 8 * nf + g];
                    mma_tf32(of[nf][0], of[nf][1], of[nf][2], of[nf][3],
                             a0, a1, a2, a3, b0, b1);
                }
            }
        }
        __syncthreads();
    }

    {
        float inv0 = 1.f / l0;
        float inv1 = 1.f / l1;
        float* o_r0 = O + (size_t)(q0 + wr + g)     * D_ + h * HD_;
        float* o_r1 = O + (size_t)(q0 + wr + g + 8) * D_ + h * HD_;
        #pragma unroll
        for (int nf = 0; nf < 8; nf++) {
            int c = 8 * nf + 2 * tg;
            *(float2*)&o_r0[c] = make_float2(of[nf][0] * inv0, of[nf][1] * inv0);
            *(float2*)&o_r1[c] = make_float2(of[nf][2] * inv1, of[nf][3] * inv1);
        }
    }
}

// ---------------------------------------------------------------------------
// Launch
// ---------------------------------------------------------------------------
extern "C" void kernel_launch(void* const* d_in, const int* in_sizes, int n_in,
                              void* d_out, int out_size)
{
    const float* x    = (const float*)d_in[0];
    const float* cosp = (const float*)d_in[1];
    const float* sinp = (const float*)d_in[2];
    // d_in[3] = mask (causal tril, recomputed analytically) — unused
    const float* Wq   = (const float*)d_in[4];
    const float* Wk   = (const float*)d_in[5];
    const float* Wv   = (const float*)d_in[6];
    const float* Wo   = (const float*)d_in[7];
    const float* qn_w = (const float*)d_in[8];
    const float* kn_w = (const float*)d_in[9];
    float* out = (float*)d_out;

    float *qkvp, *ap;
    cudaGetSymbolAddress((void**)&qkvp, g_qkv);
    cudaGetSymbolAddress((void**)&ap, g_att);

    // Fused QKV projection (fp16 tensor cores)
    qkv_gemm_kernel<<<dim3(24, S_ / 128), 256>>>(x, Wq, Wk, Wv, qkvp);

    // rmsnorm + RoPE (in place on packed buffer)
    rms_rope_kernel<<<S_, 256>>>(qkvp,        QKVW, D_,  qn_w, cosp, sinp);
    rms_rope_kernel<<<S_, 256>>>(qkvp + D_,   QKVW, KD_, kn_w, cosp, sinp);

    // Causal GQA flash attention (tf32 tensor cores)
    flash_mma_kernel<<<dim3(S_ / 64, H_), 128>>>(qkvp, qkvp + D_, qkvp + D_ + KD_, ap);

    // Output projection (fp16 tensor cores)
    wo_gemm_kernel<<<dim3(16, 16), 256>>>(ap, Wo, out);
}

// round 10
// speedup vs baseline: 3.3481x; 1.1809x over previous
#include <cuda_runtime.h>
#include <cuda_fp16.h>
#include <cuda_bf16.h>
#include <cstdint>

// Problem constants
#define S_   2048
#define D_   2048
#define H_   32
#define KVH_ 8
#define HD_  64
#define KD_  512    // KVH*HD
#define QKVW 3072   // packed qkv row width: q[0,2048) k[2048,2560) v[2560,3072)
#define EPS_ 1e-5f

// ---------------------------------------------------------------------------
// Scratch (no allocations allowed -> __device__ globals)
// ---------------------------------------------------------------------------
__device__ float g_qkv[S_ * QKVW];  // packed q|k|v after proj (later norm+rope)
__device__ float g_att[S_ * D_];    // attention output (S, H*HD)

// ---------------------------------------------------------------------------
// Helpers
// ---------------------------------------------------------------------------
__device__ __forceinline__ uint32_t pack_h2(float lo, float hi) {
    __half2 h = __floats2half2_rn(lo, hi);
    return *reinterpret_cast<uint32_t*>(&h);
}

__device__ __forceinline__ void mma_f16(
    float& c0, float& c1, float& c2, float& c3,
    uint32_t a0, uint32_t a1, uint32_t a2, uint32_t a3,
    uint32_t b0, uint32_t b1)
{
    asm volatile(
        "mma.sync.aligned.m16n8k16.row.col.f32.f16.f16.f32 "
        "{%0,%1,%2,%3}, {%4,%5,%6,%7}, {%8,%9}, {%0,%1,%2,%3};\n"
        : "+f"(c0), "+f"(c1), "+f"(c2), "+f"(c3)
        : "r"(a0), "r"(a1), "r"(a2), "r"(a3), "r"(b0), "r"(b1));
}

__device__ __forceinline__ void ldsm_x4(
    uint32_t& r0, uint32_t& r1, uint32_t& r2, uint32_t& r3, uint32_t addr)
{
    asm volatile("ldmatrix.sync.aligned.m8n8.x4.shared.b16 {%0,%1,%2,%3}, [%4];\n"
                 : "=r"(r0), "=r"(r1), "=r"(r2), "=r"(r3) : "r"(addr));
}

__device__ __forceinline__ void ldsm_x4_t(
    uint32_t& r0, uint32_t& r1, uint32_t& r2, uint32_t& r3, uint32_t addr)
{
    asm volatile("ldmatrix.sync.aligned.m8n8.x4.trans.shared.b16 {%0,%1,%2,%3}, [%4];\n"
                 : "=r"(r0), "=r"(r1), "=r"(r2), "=r"(r3) : "r"(addr));
}

// ---------------------------------------------------------------------------
// FP16 tensor-core GEMM core: C[128 rows][128 cols] tile of A[M,K]@B[K,N].
// GK=32, 256 threads (8 warps 2x4, warp tile 64x32), m16n8k16, f32 accum.
// ---------------------------------------------------------------------------
#define GK  32
#define AST 40    // As row stride in halves
#define BST 136   // Bs row stride in halves

__device__ __forceinline__ void hgemm_core(
    const float* __restrict__ A, int lda,
    const float* __restrict__ B, int ldb,
    float* __restrict__ C, int ldc,
    int K, int brow, int bcol, int ccol)
{
    __shared__ __half As[128 * AST];
    __shared__ __half Bs[GK * BST];

    const int tid  = threadIdx.x;
    const int wid  = tid >> 5;
    const int lane = tid & 31;
    const int g    = lane >> 2;
    const int tg   = lane & 3;
    const int wm   = (wid & 1) * 64;
    const int wn   = (wid >> 1) * 32;

    const int a_m  = tid >> 1;
    const int a_k0 = (tid & 1) * 16;
    const int b_k  = tid >> 3;
    const int b_n0 = (tid & 7) * 16;

    const int l15 = lane & 15;
    const int lhi = lane >> 4;

    float c[4][4][4];
    #pragma unroll
    for (int i = 0; i < 4; i++)
        #pragma unroll
        for (int j = 0; j < 4; j++)
            #pragma unroll
            for (int r = 0; r < 4; r++) c[i][j][r] = 0.f;

    for (int k0 = 0; k0 < K; k0 += GK) {
        #pragma unroll
        for (int j = 0; j < 4; j++) {
            float4 v = *(const float4*)&A[(size_t)(brow + a_m) * lda + k0 + a_k0 + 4 * j];
            uint2 h = make_uint2(pack_h2(v.x, v.y), pack_h2(v.z, v.w));
            *(uint2*)&As[a_m * AST + a_k0 + 4 * j] = h;
        }
        #pragma unroll
        for (int j = 0; j < 4; j++) {
            float4 v = *(const float4*)&B[(size_t)(k0 + b_k) * ldb + bcol + b_n0 + 4 * j];
            uint2 h = make_uint2(pack_h2(v.x, v.y), pack_h2(v.z, v.w));
            *(uint2*)&Bs[b_k * BST + b_n0 + 4 * j] = h;
        }
        __syncthreads();

        #pragma unroll
        for (int ks = 0; ks < 2; ks++) {
            uint32_t af[4][4];
            #pragma unroll
            for (int mf = 0; mf < 4; mf++) {
                const __half* p = &As[(wm + mf * 16 + l15) * AST + ks * 16 + lhi * 8];
                ldsm_x4(af[mf][0], af[mf][1], af[mf][2], af[mf][3],
                        (uint32_t)__cvta_generic_to_shared(p));
            }
            uint32_t bf[2][4];
            #pragma unroll
            for (int nb = 0; nb < 2; nb++) {
                const __half* p = &Bs[(ks * 16 + l15) * BST + wn + nb * 16 + lhi * 8];
                ldsm_x4_t(bf[nb][0], bf[nb][1], bf[nb][2], bf[nb][3],
                          (uint32_t)__cvta_generic_to_shared(p));
            }
            #pragma unroll
            for (int mf = 0; mf < 4; mf++)
                #pragma unroll
                for (int nf = 0; nf < 4; nf++) {
                    int nb = nf >> 1, hi = (nf & 1) * 2;
                    mma_f16(c[mf][nf][0], c[mf][nf][1], c[mf][nf][2], c[mf][nf][3],
                            af[mf][0], af[mf][1], af[mf][2], af[mf][3],
                            bf[nb][hi], bf[nb][hi + 1]);
                }
        }
        __syncthreads();
    }

    #pragma unroll
    for (int mf = 0; mf < 4; mf++) {
        int r0 = brow + wm + 16 * mf + g;
        #pragma unroll
        for (int nf = 0; nf < 4; nf++) {
            int cc = ccol + wn + 8 * nf + 2 * tg;
            *(float2*)&C[(size_t)r0 * ldc + cc]       = make_float2(c[mf][nf][0], c[mf][nf][1]);
            *(float2*)&C[(size_t)(r0 + 8) * ldc + cc] = make_float2(c[mf][nf][2], c[mf][nf][3]);
        }
    }
}

// Fused QKV projection: grid (24, 16).
__global__ __launch_bounds__(256, 2) void qkv_gemm_kernel(
    const float* __restrict__ x,
    const float* __restrict__ Wq, const float* __restrict__ Wk,
    const float* __restrict__ Wv, float* __restrict__ qkv)
{
    const int bx = blockIdx.x;
    const float* B; int ldb, bcol;
    if (bx < 16)      { B = Wq; ldb = D_;  bcol = bx * 128; }
    else if (bx < 20) { B = Wk; ldb = KD_; bcol = (bx - 16) * 128; }
    else              { B = Wv; ldb = KD_; bcol = (bx - 20) * 128; }
    hgemm_core(x, D_, B, ldb, qkv, QKVW, D_, blockIdx.y * 128, bcol, bx * 128);
}

// Output projection: grid (16, 16).
__global__ __launch_bounds__(256, 2) void wo_gemm_kernel(
    const float* __restrict__ A, const float* __restrict__ Wo,
    float* __restrict__ C)
{
    hgemm_core(A, D_, Wo, D_, C, D_, D_,
               blockIdx.y * 128, blockIdx.x * 128, blockIdx.x * 128);
}

// ---------------------------------------------------------------------------
// Fused rmsnorm + RoPE over a [width]-wide slice of a strided row buffer.
// ---------------------------------------------------------------------------
__global__ __launch_bounds__(256) void rms_rope_kernel(
    float* __restrict__ base, int stride, int width,
    const float* __restrict__ w,
    const float* __restrict__ cosp, const float* __restrict__ sinp)
{
    const int s = blockIdx.x;
    float* row = base + (size_t)s * stride;
    const int tid = threadIdx.x;

    float ss = 0.f;
    for (int i = tid; i < width; i += 256) {
        float v = row[i];
        ss += v * v;
    }
    #pragma unroll
    for (int o = 16; o; o >>= 1) ss += __shfl_xor_sync(0xffffffffu, ss, o);

    __shared__ float red[8];
    __shared__ float s_r;
    if ((tid & 31) == 0) red[tid >> 5] = ss;
    __syncthreads();
    if (tid == 0) {
        float t = 0.f;
        #pragma unroll
        for (int i = 0; i < 8; i++) t += red[i];
        s_r = rsqrtf(t / (float)width + EPS_);
    }
    __syncthreads();
    const float r = s_r;

    const float* cr = cosp + (size_t)s * HD_;
    const float* sr = sinp + (size_t)s * HD_;
    const int npairs = width >> 1;
    for (int p = tid; p < npairs; p += 256) {
        int head = p >> 5;
        int d    = p & 31;
        int i0 = head * HD_ + d;
        int i1 = i0 + 32;
        float v0 = row[i0] * r * w[i0];
        float v1 = row[i1] * r * w[i1];
        float c0 = cr[d],      s0 = sr[d];
        float c1 = cr[d + 32], s1 = sr[d + 32];
        row[i0] = v0 * c0 - v1 * s0;
        row[i1] = v1 * c1 + v0 * s1;
    }
}

// ---------------------------------------------------------------------------
// Flash attention, fp16 mma m16n8k16 + ldmatrix, causal, GQA.
// grid = (S/64, H), 128 threads (4 warps); warp = 16 q rows x 64 kv cols.
// Ks [n][d] fp16 (non-trans ldsm -> QK^T B-frags), Vs [kv][d] (trans ldsm),
// Ps [m][kv] per-warp P tile (non-trans ldsm A-frags); Q pre-staged via Ps.
// All strides 72 halves (144B = 9 x 16B units -> conflict-free LDSM).
// ---------------------------------------------------------------------------
#define FST 72

__global__ __launch_bounds__(128) void flash_mma_kernel(
    const float* __restrict__ Q, const float* __restrict__ K,
    const float* __restrict__ V, float* __restrict__ O)
{
    __shared__ __half Ks[64 * FST];
    __shared__ __half Vs[64 * FST];
    __shared__ __half Ps[64 * FST];   // Q staging, then per-warp P tiles

    const int tid  = threadIdx.x;
    const int wid  = tid >> 5;
    const int lane = tid & 31;
    const int g    = lane >> 2;
    const int tg   = lane & 3;
    const int wr   = wid * 16;        // warp's q-row offset
    const int l15  = lane & 15;
    const int lhi  = lane >> 4;
    // QK^T B-frag ldsm addressing (4 8x8 tiles: n-lo/k-lo, n-lo/k-hi, n-hi/k-lo, n-hi/k-hi)
    const int bt   = lane >> 3;       // tile 0..3
    const int bj   = lane & 7;
    const int brow_ = ((bt >> 1) * 8) + bj;  // row within 16-n block
    const int bcol_ = (bt & 1) * 8;          // col-half within 16-k step

    const int q0 = blockIdx.x * 64;
    const int h  = blockIdx.y;
    const int kh = h >> 2;

    // staging indices: 2 threads per row, 32 d each
    const int ld_n  = tid >> 1;
    const int ld_d0 = (tid & 1) * 32;

    // ---- stage Q (scaled) into Ps, then load A-fragments ----
    {
        const float* qrow = Q + (size_t)(q0 + ld_n) * QKVW + h * HD_ + ld_d0;
        #pragma unroll
        for (int i = 0; i < 4; i++) {
            float4 u = *(const float4*)(qrow + 8 * i);
            float4 v = *(const float4*)(qrow + 8 * i + 4);
            uint4 hh = make_uint4(pack_h2(u.x * 0.125f, u.y * 0.125f),
                                  pack_h2(u.z * 0.125f, u.w * 0.125f),
                                  pack_h2(v.x * 0.125f, v.y * 0.125f),
                                  pack_h2(v.z * 0.125f, v.w * 0.125f));
            *(uint4*)&Ps[ld_n * FST + ld_d0 + 8 * i] = hh;
        }
    }
    __syncthreads();

    uint32_t qf[4][4];
    #pragma unroll
    for (int ks = 0; ks < 4; ks++) {
        const __half* p = &Ps[(wr + l15) * FST + ks * 16 + lhi * 8];
        ldsm_x4(qf[ks][0], qf[ks][1], qf[ks][2], qf[ks][3],
                (uint32_t)__cvta_generic_to_shared(p));
    }

    float of[8][4];
    #pragma unroll
    for (int nf = 0; nf < 8; nf++)
        #pragma unroll
        for (int r = 0; r < 4; r++) of[nf][r] = 0.f;
    float m0 = -1e30f, m1 = -1e30f, l0 = 0.f, l1 = 0.f;

    for (int n0 = 0; n0 <= q0; n0 += 64) {
        // ---- stage K, V tiles (fp16, natural layout) ----
        {
            const float* krow = K + (size_t)(n0 + ld_n) * QKVW + kh * HD_ + ld_d0;
            const float* vrow = V + (size_t)(n0 + ld_n) * QKVW + kh * HD_ + ld_d0;
            #pragma unroll
            for (int i = 0; i < 4; i++) {
                float4 u = *(const float4*)(krow + 8 * i);
                float4 v = *(const float4*)(krow + 8 * i + 4);
                uint4 hh = make_uint4(pack_h2(u.x, u.y), pack_h2(u.z, u.w),
                                      pack_h2(v.x, v.y), pack_h2(v.z, v.w));
                *(uint4*)&Ks[ld_n * FST + ld_d0 + 8 * i] = hh;
                u = *(const float4*)(vrow + 8 * i);
                v = *(const float4*)(vrow + 8 * i + 4);
                hh = make_uint4(pack_h2(u.x, u.y), pack_h2(u.z, u.w),
                                pack_h2(v.x, v.y), pack_h2(v.z, v.w));
                *(uint4*)&Vs[ld_n * FST + ld_d0 + 8 * i] = hh;
            }
        }
        __syncthreads();

        // ---- S = Q K^T (16x64 per warp), fp32 accum ----
        float sf[8][4];
        #pragma unroll
        for (int nf = 0; nf < 8; nf++)
            #pragma unroll
            for (int r = 0; r < 4; r++) sf[nf][r] = 0.f;

        #pragma unroll
        for (int ks = 0; ks < 4; ks++) {
            uint32_t bf[4][4];
            #pragma unroll
            for (int nb = 0; nb < 4; nb++) {
                const __half* p = &Ks[(nb * 16 + brow_) * FST + ks * 16 + bcol_];
                ldsm_x4(bf[nb][0], bf[nb][1], bf[nb][2], bf[nb][3],
                        (uint32_t)__cvta_generic_to_shared(p));
            }
            #pragma unroll
            for (int nf = 0; nf < 8; nf++) {
                int nb = nf >> 1, o = (nf & 1) * 2;
                mma_f16(sf[nf][0], sf[nf][1], sf[nf][2], sf[nf][3],
                        qf[ks][0], qf[ks][1], qf[ks][2], qf[ks][3],
                        bf[nb][o], bf[nb][o + 1]);
            }
        }

        // ---- causal mask (diagonal tile only) ----
        if (n0 == q0) {
            #pragma unroll
            for (int nf = 0; nf < 8; nf++) {
                int c = 8 * nf + 2 * tg;
                if (c     > wr + g)     sf[nf][0] = -1e30f;
                if (c + 1 > wr + g)     sf[nf][1] = -1e30f;
                if (c     > wr + g + 8) sf[nf][2] = -1e30f;
                if (c + 1 > wr + g + 8) sf[nf][3] = -1e30f;
            }
        }

        // ---- online softmax (rows g, g+8; reduce over 4 tg lanes) ----
        {
            float tm0 = -1e30f, tm1 = -1e30f;
            #pragma unroll
            for (int nf = 0; nf < 8; nf++) {
                tm0 = fmaxf(tm0, fmaxf(sf[nf][0], sf[nf][1]));
                tm1 = fmaxf(tm1, fmaxf(sf[nf][2], sf[nf][3]));
            }
            #pragma unroll
            for (int o = 1; o <= 2; o <<= 1) {
                tm0 = fmaxf(tm0, __shfl_xor_sync(0xffffffffu, tm0, o));
                tm1 = fmaxf(tm1, __shfl_xor_sync(0xffffffffu, tm1, o));
            }
            float mn0 = fmaxf(m0, tm0);
            float mn1 = fmaxf(m1, tm1);
            float cor0 = __expf(m0 - mn0);
            float cor1 = __expf(m1 - mn1);
            float rs0 = 0.f, rs1 = 0.f;
            #pragma unroll
            for (int nf = 0; nf < 8; nf++) {
                float p0 = __expf(sf[nf][0] - mn0);
                float p1 = __expf(sf[nf][1] - mn0);
                float p2 = __expf(sf[nf][2] - mn1);
                float p3 = __expf(sf[nf][3] - mn1);
                sf[nf][0] = p0; sf[nf][1] = p1; sf[nf][2] = p2; sf[nf][3] = p3;
                rs0 += p0 + p1; rs1 += p2 + p3;
            }
            #pragma unroll
            for (int o = 1; o <= 2; o <<= 1) {
                rs0 += __shfl_xor_sync(0xffffffffu, rs0, o);
                rs1 += __shfl_xor_sync(0xffffffffu, rs1, o);
            }
            l0 = l0 * cor0 + rs0;  m0 = mn0;
            l1 = l1 * cor1 + rs1;  m1 = mn1;
            #pragma unroll
            for (int nf = 0; nf < 8; nf++) {
                of[nf][0] *= cor0; of[nf][1] *= cor0;
                of[nf][2] *= cor1; of[nf][3] *= cor1;
            }
        }

        // ---- write P (fp16) into warp-private rows of Ps ----
        #pragma unroll
        for (int nf = 0; nf < 8; nf++) {
            int c = 8 * nf + 2 * tg;
            *(uint32_t*)&Ps[(wr + g)     * FST + c] = pack_h2(sf[nf][0], sf[nf][1]);
            *(uint32_t*)&Ps[(wr + g + 8) * FST + c] = pack_h2(sf[nf][2], sf[nf][3]);
        }
        __syncwarp();

        // ---- O += P @ V ----
        #pragma unroll
        for (int ks = 0; ks < 4; ks++) {
            uint32_t af[4];
            {
                const __half* p = &Ps[(wr + l15) * FST + ks * 16 + lhi * 8];
                ldsm_x4(af[0], af[1], af[2], af[3],
                        (uint32_t)__cvta_generic_to_shared(p));
            }
            #pragma unroll
            for (int nb = 0; nb < 4; nb++) {
                uint32_t vf[4];
                const __half* p = &Vs[(ks * 16 + l15) * FST + nb * 16 + lhi * 8];
                ldsm_x4_t(vf[0], vf[1], vf[2], vf[3],
                          (uint32_t)__cvta_generic_to_shared(p));
                mma_f16(of[2*nb][0], of[2*nb][1], of[2*nb][2], of[2*nb][3],
                        af[0], af[1], af[2], af[3], vf[0], vf[1]);
                mma_f16(of[2*nb+1][0], of[2*nb+1][1], of[2*nb+1][2], of[2*nb+1][3],
                        af[0], af[1], af[2], af[3], vf[2], vf[3]);
            }
        }
        __syncthreads();   // before next tile overwrites Ks/Vs
    }

    // ---- finalize ----
    {
        float inv0 = 1.f / l0;
        float inv1 = 1.f / l1;
        float* o_r0 = O + (size_t)(q0 + wr + g)     * D_ + h * HD_;
        float* o_r1 = O + (size_t)(q0 + wr + g + 8) * D_ + h * HD_;
        #pragma unroll
        for (int nf = 0; nf < 8; nf++) {
            int c = 8 * nf + 2 * tg;
            *(float2*)&o_r0[c] = make_float2(of[nf][0] * inv0, of[nf][1] * inv0);
            *(float2*)&o_r1[c] = make_float2(of[nf][2] * inv1, of[nf][3] * inv1);
        }
    }
}

// ---------------------------------------------------------------------------
// Launch
// ---------------------------------------------------------------------------
extern "C" void kernel_launch(void* const* d_in, const int* in_sizes, int n_in,
                              void* d_out, int out_size)
{
    const float* x    = (const float*)d_in[0];
    const float* cosp = (const float*)d_in[1];
    const float* sinp = (const float*)d_in[2];
    // d_in[3] = mask (causal tril, recomputed analytically) — unused
    const float* Wq   = (const float*)d_in[4];
    const float* Wk   = (const float*)d_in[5];
    const float* Wv   = (const float*)d_in[6];
    const float* Wo   = (const float*)d_in[7];
    const float* qn_w = (const float*)d_in[8];
    const float* kn_w = (const float*)d_in[9];
    float* out = (float*)d_out;

    float *qkvp, *ap;
    cudaGetSymbolAddress((void**)&qkvp, g_qkv);
    cudaGetSymbolAddress((void**)&ap, g_att);

    // Fused QKV projection (fp16 tensor cores)
    qkv_gemm_kernel<<<dim3(24, S_ / 128), 256>>>(x, Wq, Wk, Wv, qkvp);

    // rmsnorm + RoPE (in place on packed buffer)
    rms_rope_kernel<<<S_, 256>>>(qkvp,      QKVW, D_,  qn_w, cosp, sinp);
    rms_rope_kernel<<<S_, 256>>>(qkvp + D_, QKVW, KD_, kn_w, cosp, sinp);

    // Causal GQA flash attention (fp16 mma + ldmatrix)
    flash_mma_kernel<<<dim3(S_ / 64, H_), 128>>>(qkvp, qkvp + D_, qkvp + D_ + KD_, ap);

    // Output projection (fp16 tensor cores)
    wo_gemm_kernel<<<dim3(16, 16), 256>>>(ap, Wo, out);
}

// round 12
// speedup vs baseline: 4.1770x; 1.2476x over previous
#include <cuda_runtime.h>
#include <cuda_fp16.h>
#include <cuda_bf16.h>
#include <cstdint>

// Problem constants
#define S_   2048
#define D_   2048
#define H_   32
#define KVH_ 8
#define HD_  64
#define KD_  512    // KVH*HD
#define QKVW 3072   // packed qkv row width: q[0,2048) k[2048,2560) v[2560,3072)
#define KVW  1024   // packed fp16 kv row width: k[0,512) v[512,1024)
#define EPS_ 1e-5f

// ---------------------------------------------------------------------------
// Scratch (no allocations allowed -> __device__ globals)
// ---------------------------------------------------------------------------
__device__ float  g_qkv[S_ * QKVW];  // packed q|k|v after proj (later norm+rope)
__device__ __half g_kv16[S_ * KVW];  // fp16 k (rope'd) | v, packed per row
__device__ float  g_att[S_ * D_];    // attention output (S, H*HD)

// ---------------------------------------------------------------------------
// Helpers
// ---------------------------------------------------------------------------
__device__ __forceinline__ uint32_t pack_h2(float lo, float hi) {
    __half2 h = __floats2half2_rn(lo, hi);
    return *reinterpret_cast<uint32_t*>(&h);
}

__device__ __forceinline__ void mma_f16(
    float& c0, float& c1, float& c2, float& c3,
    uint32_t a0, uint32_t a1, uint32_t a2, uint32_t a3,
    uint32_t b0, uint32_t b1)
{
    asm volatile(
        "mma.sync.aligned.m16n8k16.row.col.f32.f16.f16.f32 "
        "{%0,%1,%2,%3}, {%4,%5,%6,%7}, {%8,%9}, {%0,%1,%2,%3};\n"
        : "+f"(c0), "+f"(c1), "+f"(c2), "+f"(c3)
        : "r"(a0), "r"(a1), "r"(a2), "r"(a3), "r"(b0), "r"(b1));
}

__device__ __forceinline__ void ldsm_x4(
    uint32_t& r0, uint32_t& r1, uint32_t& r2, uint32_t& r3, uint32_t addr)
{
    asm volatile("ldmatrix.sync.aligned.m8n8.x4.shared.b16 {%0,%1,%2,%3}, [%4];\n"
                 : "=r"(r0), "=r"(r1), "=r"(r2), "=r"(r3) : "r"(addr));
}

__device__ __forceinline__ void ldsm_x4_t(
    uint32_t& r0, uint32_t& r1, uint32_t& r2, uint32_t& r3, uint32_t addr)
{
    asm volatile("ldmatrix.sync.aligned.m8n8.x4.trans.shared.b16 {%0,%1,%2,%3}, [%4];\n"
                 : "=r"(r0), "=r"(r1), "=r"(r2), "=r"(r3) : "r"(addr));
}

// ---------------------------------------------------------------------------
// FP16 tensor-core GEMM core (unchanged, validated).
// ---------------------------------------------------------------------------
#define GK  32
#define AST 40
#define BST 136

__device__ __forceinline__ void hgemm_core(
    const float* __restrict__ A, int lda,
    const float* __restrict__ B, int ldb,
    float* __restrict__ C, int ldc,
    int K, int brow, int bcol, int ccol)
{
    __shared__ __half As[128 * AST];
    __shared__ __half Bs[GK * BST];

    const int tid  = threadIdx.x;
    const int wid  = tid >> 5;
    const int lane = tid & 31;
    const int g    = lane >> 2;
    const int tg   = lane & 3;
    const int wm   = (wid & 1) * 64;
    const int wn   = (wid >> 1) * 32;

    const int a_m  = tid >> 1;
    const int a_k0 = (tid & 1) * 16;
    const int b_k  = tid >> 3;
    const int b_n0 = (tid & 7) * 16;

    const int l15 = lane & 15;
    const int lhi = lane >> 4;

    float c[4][4][4];
    #pragma unroll
    for (int i = 0; i < 4; i++)
        #pragma unroll
        for (int j = 0; j < 4; j++)
            #pragma unroll
            for (int r = 0; r < 4; r++) c[i][j][r] = 0.f;

    for (int k0 = 0; k0 < K; k0 += GK) {
        #pragma unroll
        for (int j = 0; j < 4; j++) {
            float4 v = *(const float4*)&A[(size_t)(brow + a_m) * lda + k0 + a_k0 + 4 * j];
            uint2 h = make_uint2(pack_h2(v.x, v.y), pack_h2(v.z, v.w));
            *(uint2*)&As[a_m * AST + a_k0 + 4 * j] = h;
        }
        #pragma unroll
        for (int j = 0; j < 4; j++) {
            float4 v = *(const float4*)&B[(size_t)(k0 + b_k) * ldb + bcol + b_n0 + 4 * j];
            uint2 h = make_uint2(pack_h2(v.x, v.y), pack_h2(v.z, v.w));
            *(uint2*)&Bs[b_k * BST + b_n0 + 4 * j] = h;
        }
        __syncthreads();

        #pragma unroll
        for (int ks = 0; ks < 2; ks++) {
            uint32_t af[4][4];
            #pragma unroll
            for (int mf = 0; mf < 4; mf++) {
                const __half* p = &As[(wm + mf * 16 + l15) * AST + ks * 16 + lhi * 8];
                ldsm_x4(af[mf][0], af[mf][1], af[mf][2], af[mf][3],
                        (uint32_t)__cvta_generic_to_shared(p));
            }
            uint32_t bf[2][4];
            #pragma unroll
            for (int nb = 0; nb < 2; nb++) {
                const __half* p = &Bs[(ks * 16 + l15) * BST + wn + nb * 16 + lhi * 8];
                ldsm_x4_t(bf[nb][0], bf[nb][1], bf[nb][2], bf[nb][3],
                          (uint32_t)__cvta_generic_to_shared(p));
            }
            #pragma unroll
            for (int mf = 0; mf < 4; mf++)
                #pragma unroll
                for (int nf = 0; nf < 4; nf++) {
                    int nb = nf >> 1, hi = (nf & 1) * 2;
                    mma_f16(c[mf][nf][0], c[mf][nf][1], c[mf][nf][2], c[mf][nf][3],
                            af[mf][0], af[mf][1], af[mf][2], af[mf][3],
                            bf[nb][hi], bf[nb][hi + 1]);
                }
        }
        __syncthreads();
    }

    #pragma unroll
    for (int mf = 0; mf < 4; mf++) {
        int r0 = brow + wm + 16 * mf + g;
        #pragma unroll
        for (int nf = 0; nf < 4; nf++) {
            int cc = ccol + wn + 8 * nf + 2 * tg;
            *(float2*)&C[(size_t)r0 * ldc + cc]       = make_float2(c[mf][nf][0], c[mf][nf][1]);
            *(float2*)&C[(size_t)(r0 + 8) * ldc + cc] = make_float2(c[mf][nf][2], c[mf][nf][3]);
        }
    }
}

__global__ __launch_bounds__(256, 2) void qkv_gemm_kernel(
    const float* __restrict__ x,
    const float* __restrict__ Wq, const float* __restrict__ Wk,
    const float* __restrict__ Wv, float* __restrict__ qkv)
{
    const int bx = blockIdx.x;
    const float* B; int ldb, bcol;
    if (bx < 16)      { B = Wq; ldb = D_;  bcol = bx * 128; }
    else if (bx < 20) { B = Wk; ldb = KD_; bcol = (bx - 16) * 128; }
    else              { B = Wv; ldb = KD_; bcol = (bx - 20) * 128; }
    hgemm_core(x, D_, B, ldb, qkv, QKVW, D_, blockIdx.y * 128, bcol, bx * 128);
}

__global__ __launch_bounds__(256, 2) void wo_gemm_kernel(
    const float* __restrict__ A, const float* __restrict__ Wo,
    float* __restrict__ C)
{
    hgemm_core(A, D_, Wo, D_, C, D_, D_,
               blockIdx.y * 128, blockIdx.x * 128, blockIdx.x * 128);
}

// ---------------------------------------------------------------------------
// Fused rmsnorm + RoPE; optionally mirrors the result as fp16 into out16
// (used for K so flash reads fp16 directly).
// ---------------------------------------------------------------------------
__global__ __launch_bounds__(256) void rms_rope_kernel(
    float* __restrict__ base, int stride, int width,
    const float* __restrict__ w,
    const float* __restrict__ cosp, const float* __restrict__ sinp,
    __half* __restrict__ out16, int stride16)
{
    const int s = blockIdx.x;
    float* row = base + (size_t)s * stride;
    const int tid = threadIdx.x;

    float ss = 0.f;
    for (int i = tid; i < width; i += 256) {
        float v = row[i];
        ss += v * v;
    }
    #pragma unroll
    for (int o = 16; o; o >>= 1) ss += __shfl_xor_sync(0xffffffffu, ss, o);

    __shared__ float red[8];
    __shared__ float s_r;
    if ((tid & 31) == 0) red[tid >> 5] = ss;
    __syncthreads();
    if (tid == 0) {
        float t = 0.f;
        #pragma unroll
        for (int i = 0; i < 8; i++) t += red[i];
        s_r = rsqrtf(t / (float)width + EPS_);
    }
    __syncthreads();
    const float r = s_r;

    const float* cr = cosp + (size_t)s * HD_;
    const float* sr = sinp + (size_t)s * HD_;
    __half* o16 = out16 ? out16 + (size_t)s * stride16 : nullptr;
    const int npairs = width >> 1;
    for (int p = tid; p < npairs; p += 256) {
        int head = p >> 5;
        int d    = p & 31;
        int i0 = head * HD_ + d;
        int i1 = i0 + 32;
        float v0 = row[i0] * r * w[i0];
        float v1 = row[i1] * r * w[i1];
        float c0 = cr[d],      s0 = sr[d];
        float c1 = cr[d + 32], s1 = sr[d + 32];
        float o0 = v0 * c0 - v1 * s0;
        float o1 = v1 * c1 + v0 * s1;
        row[i0] = o0;
        row[i1] = o1;
        if (o16) {
            o16[i0] = __float2half(o0);
            o16[i1] = __float2half(o1);
        }
    }
}

// V fp32 -> fp16 into packed kv buffer. grid = S, 256 threads.
__global__ __launch_bounds__(256) void v2h_kernel(
    const float* __restrict__ vbase, __half* __restrict__ kv16)
{
    const int s = blockIdx.x;
    const int t = threadIdx.x;
    const float* src = vbase + (size_t)s * QKVW;
    __half* dst = kv16 + (size_t)s * KVW + KD_;
    float2 u = *(const float2*)(src + t * 2);
    *(uint32_t*)&dst[t * 2] = pack_h2(u.x, u.y);
}

// ---------------------------------------------------------------------------
// Flash attention v3: fp16 mma + ldmatrix, BM=128 (8 warps / 256 thr,
// 2 CTAs/SM), fp16 K/V staged as raw uint4 copies from g_kv16, causal warp
// skip, heavy-q blocks scheduled first. grid = (S/128, H).
// ---------------------------------------------------------------------------
#define FST 72

__global__ __launch_bounds__(256, 2) void flash_mma_kernel(
    const float* __restrict__ Q, const __half* __restrict__ KV16,
    float* __restrict__ O)
{
    __shared__ __half Ks[64 * FST];
    __shared__ __half Vs[64 * FST];
    __shared__ __half Ps[128 * FST];  // Q staging, then per-warp P tiles

    const int tid  = threadIdx.x;
    const int wid  = tid >> 5;
    const int lane = tid & 31;
    const int g    = lane >> 2;
    const int tg   = lane & 3;
    const int wr   = wid * 16;        // warp's q-row offset within 128-row tile
    const int l15  = lane & 15;
    const int lhi  = lane >> 4;
    const int bt   = lane >> 3;
    const int bj   = lane & 7;
    const int brow_ = ((bt >> 1) * 8) + bj;
    const int bcol_ = (bt & 1) * 8;

    const int q0 = (gridDim.x - 1 - blockIdx.x) * 128;  // heavy blocks first
    const int h  = blockIdx.y;
    const int kh = h >> 2;
    const int qw = q0 + wr;           // warp's first global q row

    // ---- stage Q (scaled) into Ps, load A-fragments once ----
    {
        int row = tid >> 1;           // 0..127
        int d0  = (tid & 1) * 32;
        const float* qrow = Q + (size_t)(q0 + row) * QKVW + h * HD_ + d0;
        #pragma unroll
        for (int i = 0; i < 4; i++) {
            float4 u = *(const float4*)(qrow + 8 * i);
            float4 v = *(const float4*)(qrow + 8 * i + 4);
            uint4 hh = make_uint4(pack_h2(u.x * 0.125f, u.y * 0.125f),
                                  pack_h2(u.z * 0.125f, u.w * 0.125f),
                                  pack_h2(v.x * 0.125f, v.y * 0.125f),
                                  pack_h2(v.z * 0.125f, v.w * 0.125f));
            *(uint4*)&Ps[row * FST + d0 + 8 * i] = hh;
        }
    }
    __syncthreads();

    uint32_t qf[4][4];
    #pragma unroll
    for (int ks = 0; ks < 4; ks++) {
        const __half* p = &Ps[(wr + l15) * FST + ks * 16 + lhi * 8];
        ldsm_x4(qf[ks][0], qf[ks][1], qf[ks][2], qf[ks][3],
                (uint32_t)__cvta_generic_to_shared(p));
    }
    __syncthreads();   // Ps reused as P tiles below

    float of[8][4];
    #pragma unroll
    for (int nf = 0; nf < 8; nf++)
        #pragma unroll
        for (int r = 0; r < 4; r++) of[nf][r] = 0.f;
    float m0 = -1e30f, m1 = -1e30f, l0 = 0.f, l1 = 0.f;

    // K/V staging: thread -> (row = tid>>2, 16-half chunk = (tid&3)*16)
    const int kv_r = tid >> 2;
    const int kv_c = (tid & 3) * 16;

    for (int n0 = 0; n0 <= q0 + 64; n0 += 64) {
        // ---- stage K, V tiles: raw fp16 copies ----
        {
            const __half* ksrc = KV16 + (size_t)(n0 + kv_r) * KVW + kh * HD_ + kv_c;
            const __half* vsrc = ksrc + KD_;
            *(uint4*)&Ks[kv_r * FST + kv_c]     = *(const uint4*)ksrc;
            *(uint4*)&Ks[kv_r * FST + kv_c + 8] = *(const uint4*)(ksrc + 8);
            *(uint4*)&Vs[kv_r * FST + kv_c]     = *(const uint4*)vsrc;
            *(uint4*)&Vs[kv_r * FST + kv_c + 8] = *(const uint4*)(vsrc + 8);
        }
        __syncthreads();

        if (n0 <= qw + 15) {   // warp not fully masked for this tile
            // ---- S = Q K^T (16x64 per warp) ----
            float sf[8][4];
            #pragma unroll
            for (int nf = 0; nf < 8; nf++)
                #pragma unroll
                for (int r = 0; r < 4; r++) sf[nf][r] = 0.f;

            #pragma unroll
            for (int ks = 0; ks < 4; ks++) {
                uint32_t bf[4][4];
                #pragma unroll
                for (int nb = 0; nb < 4; nb++) {
                    const __half* p = &Ks[(nb * 16 + brow_) * FST + ks * 16 + bcol_];
                    ldsm_x4(bf[nb][0], bf[nb][1], bf[nb][2], bf[nb][3],
                            (uint32_t)__cvta_generic_to_shared(p));
                }
                #pragma unroll
                for (int nf = 0; nf < 8; nf++) {
                    int nb = nf >> 1, o = (nf & 1) * 2;
                    mma_f16(sf[nf][0], sf[nf][1], sf[nf][2], sf[nf][3],
                            qf[ks][0], qf[ks][1], qf[ks][2], qf[ks][3],
                            bf[nb][o], bf[nb][o + 1]);
                }
            }

            // ---- causal mask ----
            if (n0 + 63 > qw) {
                int r0 = qw + g - n0;
                int r1 = r0 + 8;
                #pragma unroll
                for (int nf = 0; nf < 8; nf++) {
                    int c = 8 * nf + 2 * tg;
                    if (c     > r0) sf[nf][0] = -1e30f;
                    if (c + 1 > r0) sf[nf][1] = -1e30f;
                    if (c     > r1) sf[nf][2] = -1e30f;
                    if (c + 1 > r1) sf[nf][3] = -1e30f;
                }
            }

            // ---- online softmax ----
            {
                float tm0 = -1e30f, tm1 = -1e30f;
                #pragma unroll
                for (int nf = 0; nf < 8; nf++) {
                    tm0 = fmaxf(tm0, fmaxf(sf[nf][0], sf[nf][1]));
                    tm1 = fmaxf(tm1, fmaxf(sf[nf][2], sf[nf][3]));
                }
                #pragma unroll
                for (int o = 1; o <= 2; o <<= 1) {
                    tm0 = fmaxf(tm0, __shfl_xor_sync(0xffffffffu, tm0, o));
                    tm1 = fmaxf(tm1, __shfl_xor_sync(0xffffffffu, tm1, o));
                }
                float mn0 = fmaxf(m0, tm0);
                float mn1 = fmaxf(m1, tm1);
                float cor0 = __expf(m0 - mn0);
                float cor1 = __expf(m1 - mn1);
                float rs0 = 0.f, rs1 = 0.f;
                #pragma unroll
                for (int nf = 0; nf < 8; nf++) {
                    float p0 = __expf(sf[nf][0] - mn0);
                    float p1 = __expf(sf[nf][1] - mn0);
                    float p2 = __expf(sf[nf][2] - mn1);
                    float p3 = __expf(sf[nf][3] - mn1);
                    sf[nf][0] = p0; sf[nf][1] = p1; sf[nf][2] = p2; sf[nf][3] = p3;
                    rs0 += p0 + p1; rs1 += p2 + p3;
                }
                #pragma unroll
                for (int o = 1; o <= 2; o <<= 1) {
                    rs0 += __shfl_xor_sync(0xffffffffu, rs0, o);
                    rs1 += __shfl_xor_sync(0xffffffffu, rs1, o);
                }
                l0 = l0 * cor0 + rs0;  m0 = mn0;
                l1 = l1 * cor1 + rs1;  m1 = mn1;
                #pragma unroll
                for (int nf = 0; nf < 8; nf++) {
                    of[nf][0] *= cor0; of[nf][1] *= cor0;
                    of[nf][2] *= cor1; of[nf][3] *= cor1;
                }
            }

            // ---- write P (fp16) into warp-private rows of Ps ----
            #pragma unroll
            for (int nf = 0; nf < 8; nf++) {
                int c = 8 * nf + 2 * tg;
                *(uint32_t*)&Ps[(wr + g)     * FST + c] = pack_h2(sf[nf][0], sf[nf][1]);
                *(uint32_t*)&Ps[(wr + g + 8) * FST + c] = pack_h2(sf[nf][2], sf[nf][3]);
            }
            __syncwarp();

            // ---- O += P @ V ----
            #pragma unroll
            for (int ks = 0; ks < 4; ks++) {
                uint32_t af[4];
                {
                    const __half* p = &Ps[(wr + l15) * FST + ks * 16 + lhi * 8];
                    ldsm_x4(af[0], af[1], af[2], af[3],
                            (uint32_t)__cvta_generic_to_shared(p));
                }
                #pragma unroll
                for (int nb = 0; nb < 4; nb++) {
                    uint32_t vf[4];
                    const __half* p = &Vs[(ks * 16 + l15) * FST + nb * 16 + lhi * 8];
                    ldsm_x4_t(vf[0], vf[1], vf[2], vf[3],
                              (uint32_t)__cvta_generic_to_shared(p));
                    mma_f16(of[2*nb][0], of[2*nb][1], of[2*nb][2], of[2*nb][3],
                            af[0], af[1], af[2], af[3], vf[0], vf[1]);
                    mma_f16(of[2*nb+1][0], of[2*nb+1][1], of[2*nb+1][2], of[2*nb+1][3],
                            af[0], af[1], af[2], af[3], vf[2], vf[3]);
                }
            }
        }
        __syncthreads();   // before next tile overwrites Ks/Vs
    }

    // ---- finalize ----
    {
        float inv0 = 1.f / l0;
        float inv1 = 1.f / l1;
        float* o_r0 = O + (size_t)(q0 + wr + g)     * D_ + h * HD_;
        float* o_r1 = O + (size_t)(q0 + wr + g + 8) * D_ + h * HD_;
        #pragma unroll
        for (int nf = 0; nf < 8; nf++) {
            int c = 8 * nf + 2 * tg;
            *(float2*)&o_r0[c] = make_float2(of[nf][0] * inv0, of[nf][1] * inv0);
            *(float2*)&o_r1[c] = make_float2(of[nf][2] * inv1, of[nf][3] * inv1);
        }
    }
}

// ---------------------------------------------------------------------------
// Launch
// ---------------------------------------------------------------------------
extern "C" void kernel_launch(void* const* d_in, const int* in_sizes, int n_in,
                              void* d_out, int out_size)
{
    const float* x    = (const float*)d_in[0];
    const float* cosp = (const float*)d_in[1];
    const float* sinp = (const float*)d_in[2];
    // d_in[3] = mask (causal tril, recomputed analytically) — unused
    const float* Wq   = (const float*)d_in[4];
    const float* Wk   = (const float*)d_in[5];
    const float* Wv   = (const float*)d_in[6];
    const float* Wo   = (const float*)d_in[7];
    const float* qn_w = (const float*)d_in[8];
    const float* kn_w = (const float*)d_in[9];
    float* out = (float*)d_out;

    float *qkvp, *ap;
    __half* kv16p;
    cudaGetSymbolAddress((void**)&qkvp, g_qkv);
    cudaGetSymbolAddress((void**)&kv16p, g_kv16);
    cudaGetSymbolAddress((void**)&ap, g_att);

    // Fused QKV projection (fp16 tensor cores)
    qkv_gemm_kernel<<<dim3(24, S_ / 128), 256>>>(x, Wq, Wk, Wv, qkvp);

    // rmsnorm + RoPE; K also mirrored to fp16 kv buffer
    rms_rope_kernel<<<S_, 256>>>(qkvp,      QKVW, D_,  qn_w, cosp, sinp,
                                 (half*)nullptr, 0);
    rms_rope_kernel<<<S_, 256>>>(qkvp + D_, QKVW, KD_, kn_w, cosp, sinp,
                                 kv16p, KVW);
    // V -> fp16 kv buffer
    v2h_kernel<<<S_, 256>>>(qkvp + D_ + KD_, kv16p);

    // Causal GQA flash attention (fp16 mma + ldmatrix, BM=128)
    flash_mma_kernel<<<dim3(S_ / 128, H_), 256>>>(qkvp, kv16p, ap);

    // Output projection (fp16 tensor cores)
    wo_gemm_kernel<<<dim3(16, 16), 256>>>(ap, Wo, out);
}

// round 13
// speedup vs baseline: 6.9553x; 1.6652x over previous
#include <cuda_runtime.h>
#include <cuda_fp16.h>
#include <cuda_bf16.h>
#include <cstdint>

// Problem constants
#define S_   2048
#define D_   2048
#define H_   32
#define KVH_ 8
#define HD_  64
#define KD_  512    // KVH*HD
#define QKVW 3072   // packed qkv row width: q[0,2048) k[2048,2560) v[2560,3072)
#define KVW  1024   // packed fp16 kv row width: k[0,512) v[512,1024)
#define EPS_ 1e-5f

// ---------------------------------------------------------------------------
// Scratch (no allocations allowed -> __device__ globals)
// ---------------------------------------------------------------------------
__device__ float  g_qkv[S_ * QKVW];   // packed q|k|v after proj (later norm+rope)
__device__ __half g_kv16[S_ * KVW];   // fp16 k (rope'd) | v
__device__ __half g_att16[S_ * D_];   // attention output, fp16 (A of Wo gemm)
__device__ __half g_x16[S_ * D_];     // x in fp16
__device__ __half g_wq16[D_ * D_];
__device__ __half g_wk16[D_ * KD_];
__device__ __half g_wv16[D_ * KD_];
__device__ __half g_wo16[D_ * D_];

// ---------------------------------------------------------------------------
// Helpers
// ---------------------------------------------------------------------------
__device__ __forceinline__ uint32_t pack_h2(float lo, float hi) {
    __half2 h = __floats2half2_rn(lo, hi);
    return *reinterpret_cast<uint32_t*>(&h);
}

__device__ __forceinline__ void mma_f16(
    float& c0, float& c1, float& c2, float& c3,
    uint32_t a0, uint32_t a1, uint32_t a2, uint32_t a3,
    uint32_t b0, uint32_t b1)
{
    asm volatile(
        "mma.sync.aligned.m16n8k16.row.col.f32.f16.f16.f32 "
        "{%0,%1,%2,%3}, {%4,%5,%6,%7}, {%8,%9}, {%0,%1,%2,%3};\n"
        : "+f"(c0), "+f"(c1), "+f"(c2), "+f"(c3)
        : "r"(a0), "r"(a1), "r"(a2), "r"(a3), "r"(b0), "r"(b1));
}

__device__ __forceinline__ void ldsm_x4(
    uint32_t& r0, uint32_t& r1, uint32_t& r2, uint32_t& r3, uint32_t addr)
{
    asm volatile("ldmatrix.sync.aligned.m8n8.x4.shared.b16 {%0,%1,%2,%3}, [%4];\n"
                 : "=r"(r0), "=r"(r1), "=r"(r2), "=r"(r3) : "r"(addr));
}

__device__ __forceinline__ void ldsm_x4_t(
    uint32_t& r0, uint32_t& r1, uint32_t& r2, uint32_t& r3, uint32_t addr)
{
    asm volatile("ldmatrix.sync.aligned.m8n8.x4.trans.shared.b16 {%0,%1,%2,%3}, [%4];\n"
                 : "=r"(r0), "=r"(r1), "=r"(r2), "=r"(r3) : "r"(addr));
}

__device__ __forceinline__ void cp_async16(uint32_t smem_addr, const void* gptr) {
    asm volatile("cp.async.ca.shared.global [%0], [%1], 16;\n"
                 :: "r"(smem_addr), "l"(gptr));
}
#define CP_COMMIT() asm volatile("cp.async.commit_group;\n" ::: "memory")
#define CP_WAIT0()  asm volatile("cp.async.wait_group 0;\n" ::: "memory")

// fp32 -> fp16 bulk convert; n must be a multiple of 4.
__global__ __launch_bounds__(256) void f2h_kernel(
    const float* __restrict__ src, __half* __restrict__ dst, int n)
{
    int i = (blockIdx.x * 256 + threadIdx.x) * 4;
    if (i < n) {
        float4 v = *(const float4*)(src + i);
        *(uint2*)(dst + i) = make_uint2(pack_h2(v.x, v.y), pack_h2(v.z, v.w));
    }
}

// ---------------------------------------------------------------------------
// FP16-input tensor-core GEMM core with cp.async 2-stage double buffering.
// C[128x128 tile] = A[M,K]@B[K,N]; A,B fp16 row-major, C fp32.
// GK=32, 256 threads (8 warps 2x4, warp tile 64x32), m16n8k16.
// ---------------------------------------------------------------------------
#define GK  32
#define AST 40
#define BST 136

__device__ __forceinline__ void hgemm16_core(
    const __half* __restrict__ A, int lda,
    const __half* __restrict__ B, int ldb,
    float* __restrict__ C, int ldc,
    int K, int brow, int bcol, int ccol)
{
    __shared__ __half As[2][128 * AST];
    __shared__ __half Bs[2][GK * BST];

    const int tid  = threadIdx.x;
    const int wid  = tid >> 5;
    const int lane = tid & 31;
    const int g    = lane >> 2;
    const int tg   = lane & 3;
    const int wm   = (wid & 1) * 64;
    const int wn   = (wid >> 1) * 32;
    const int l15  = lane & 15;
    const int lhi  = lane >> 4;

    // A chunks: 512 x 16B; chunk c -> row c>>2, col (c&3)*8 halves
    const int a_r0 = tid >> 2, a_co = (tid & 3) * 8;
    // B chunks: 512 x 16B; chunk c -> row c>>4, col (c&15)*8 halves
    const int b_r0 = tid >> 4, b_co = (tid & 15) * 8;

    float c[4][4][4];
    #pragma unroll
    for (int i = 0; i < 4; i++)
        #pragma unroll
        for (int j = 0; j < 4; j++)
            #pragma unroll
            for (int r = 0; r < 4; r++) c[i][j][r] = 0.f;

    const int nit = K / GK;

    // issue stage tiles for k0 into buffer buf
    auto issue = [&](int buf, int k0) {
        // A: chunks tid and tid+256
        cp_async16((uint32_t)__cvta_generic_to_shared(&As[buf][a_r0 * AST + a_co]),
                   A + (size_t)(brow + a_r0) * lda + k0 + a_co);
        cp_async16((uint32_t)__cvta_generic_to_shared(&As[buf][(a_r0 + 64) * AST + a_co]),
                   A + (size_t)(brow + a_r0 + 64) * lda + k0 + a_co);
        // B: chunks tid and tid+256
        cp_async16((uint32_t)__cvta_generic_to_shared(&Bs[buf][b_r0 * BST + b_co]),
                   B + (size_t)(k0 + b_r0) * ldb + bcol + b_co);
        cp_async16((uint32_t)__cvta_generic_to_shared(&Bs[buf][(b_r0 + 16) * BST + b_co]),
                   B + (size_t)(k0 + b_r0 + 16) * ldb + bcol + b_co);
        CP_COMMIT();
    };

    issue(0, 0);
    int buf = 0;

    for (int it = 0; it < nit; it++) {
        CP_WAIT0();
        __syncthreads();
        if (it + 1 < nit) issue(buf ^ 1, (it + 1) * GK);

        const __half* Ab = As[buf];
        const __half* Bb = Bs[buf];
        #pragma unroll
        for (int ks = 0; ks < 2; ks++) {
            uint32_t af[4][4];
            #pragma unroll
            for (int mf = 0; mf < 4; mf++) {
                const __half* p = &Ab[(wm + mf * 16 + l15) * AST + ks * 16 + lhi * 8];
                ldsm_x4(af[mf][0], af[mf][1], af[mf][2], af[mf][3],
                        (uint32_t)__cvta_generic_to_shared(p));
            }
            uint32_t bf[2][4];
            #pragma unroll
            for (int nb = 0; nb < 2; nb++) {
                const __half* p = &Bb[(ks * 16 + l15) * BST + wn + nb * 16 + lhi * 8];
                ldsm_x4_t(bf[nb][0], bf[nb][1], bf[nb][2], bf[nb][3],
                          (uint32_t)__cvta_generic_to_shared(p));
            }
            #pragma unroll
            for (int mf = 0; mf < 4; mf++)
                #pragma unroll
                for (int nf = 0; nf < 4; nf++) {
                    int nb = nf >> 1, hi = (nf & 1) * 2;
                    mma_f16(c[mf][nf][0], c[mf][nf][1], c[mf][nf][2], c[mf][nf][3],
                            af[mf][0], af[mf][1], af[mf][2], af[mf][3],
                            bf[nb][hi], bf[nb][hi + 1]);
                }
        }
        buf ^= 1;
    }

    #pragma unroll
    for (int mf = 0; mf < 4; mf++) {
        int r0 = brow + wm + 16 * mf + g;
        #pragma unroll
        for (int nf = 0; nf < 4; nf++) {
            int cc = ccol + wn + 8 * nf + 2 * tg;
            *(float2*)&C[(size_t)r0 * ldc + cc]       = make_float2(c[mf][nf][0], c[mf][nf][1]);
            *(float2*)&C[(size_t)(r0 + 8) * ldc + cc] = make_float2(c[mf][nf][2], c[mf][nf][3]);
        }
    }
}

__global__ __launch_bounds__(256, 2) void qkv_gemm_kernel(
    const __half* __restrict__ x16,
    const __half* __restrict__ Wq16, const __half* __restrict__ Wk16,
    const __half* __restrict__ Wv16, float* __restrict__ qkv)
{
    const int bx = blockIdx.x;
    const __half* B; int ldb, bcol;
    if (bx < 16)      { B = Wq16; ldb = D_;  bcol = bx * 128; }
    else if (bx < 20) { B = Wk16; ldb = KD_; bcol = (bx - 16) * 128; }
    else              { B = Wv16; ldb = KD_; bcol = (bx - 20) * 128; }
    hgemm16_core(x16, D_, B, ldb, qkv, QKVW, D_, blockIdx.y * 128, bcol, bx * 128);
}

__global__ __launch_bounds__(256, 2) void wo_gemm_kernel(
    const __half* __restrict__ A16, const __half* __restrict__ Wo16,
    float* __restrict__ C)
{
    hgemm16_core(A16, D_, Wo16, D_, C, D_, D_,
                 blockIdx.y * 128, blockIdx.x * 128, blockIdx.x * 128);
}

// ---------------------------------------------------------------------------
// Fused rmsnorm + RoPE; optionally mirrors fp16 (K path -> kv buffer).
// ---------------------------------------------------------------------------
__global__ __launch_bounds__(256) void rms_rope_kernel(
    float* __restrict__ base, int stride, int width,
    const float* __restrict__ w,
    const float* __restrict__ cosp, const float* __restrict__ sinp,
    __half* __restrict__ out16, int stride16)
{
    const int s = blockIdx.x;
    float* row = base + (size_t)s * stride;
    const int tid = threadIdx.x;

    float ss = 0.f;
    for (int i = tid; i < width; i += 256) {
        float v = row[i];
        ss += v * v;
    }
    #pragma unroll
    for (int o = 16; o; o >>= 1) ss += __shfl_xor_sync(0xffffffffu, ss, o);

    __shared__ float red[8];
    __shared__ float s_r;
    if ((tid & 31) == 0) red[tid >> 5] = ss;
    __syncthreads();
    if (tid == 0) {
        float t = 0.f;
        #pragma unroll
        for (int i = 0; i < 8; i++) t += red[i];
        s_r = rsqrtf(t / (float)width + EPS_);
    }
    __syncthreads();
    const float r = s_r;

    const float* cr = cosp + (size_t)s * HD_;
    const float* sr = sinp + (size_t)s * HD_;
    __half* o16 = out16 ? out16 + (size_t)s * stride16 : nullptr;
    const int npairs = width >> 1;
    for (int p = tid; p < npairs; p += 256) {
        int head = p >> 5;
        int d    = p & 31;
        int i0 = head * HD_ + d;
        int i1 = i0 + 32;
        float v0 = row[i0] * r * w[i0];
        float v1 = row[i1] * r * w[i1];
        float c0 = cr[d],      s0 = sr[d];
        float c1 = cr[d + 32], s1 = sr[d + 32];
        float o0 = v0 * c0 - v1 * s0;
        float o1 = v1 * c1 + v0 * s1;
        row[i0] = o0;
        row[i1] = o1;
        if (o16) {
            o16[i0] = __float2half(o0);
            o16[i1] = __float2half(o1);
        }
    }
}

// V fp32 -> fp16 into packed kv buffer. grid = S, 256 threads.
__global__ __launch_bounds__(256) void v2h_kernel(
    const float* __restrict__ vbase, __half* __restrict__ kv16)
{
    const int s = blockIdx.x;
    const int t = threadIdx.x;
    const float* src = vbase + (size_t)s * QKVW;
    __half* dst = kv16 + (size_t)s * KVW + KD_;
    float2 u = *(const float2*)(src + t * 2);
    *(uint32_t*)&dst[t * 2] = pack_h2(u.x, u.y);
}

// ---------------------------------------------------------------------------
// Flash attention: fp16 mma + ldmatrix, BM=128 (8 warps, 2 CTAs/SM),
// fp16 K/V raw copies, causal warp skip, heavy blocks first.
// Output written as fp16 to g_att16. grid = (S/128, H).
// ---------------------------------------------------------------------------
#define FST 72

__global__ __launch_bounds__(256, 2) void flash_mma_kernel(
    const float* __restrict__ Q, const __half* __restrict__ KV16,
    __half* __restrict__ O16)
{
    __shared__ __half Ks[64 * FST];
    __shared__ __half Vs[64 * FST];
    __shared__ __half Ps[128 * FST];  // Q staging, then per-warp P tiles

    const int tid  = threadIdx.x;
    const int wid  = tid >> 5;
    const int lane = tid & 31;
    const int g    = lane >> 2;
    const int tg   = lane & 3;
    const int wr   = wid * 16;
    const int l15  = lane & 15;
    const int lhi  = lane >> 4;
    const int bt   = lane >> 3;
    const int bj   = lane & 7;
    const int brow_ = ((bt >> 1) * 8) + bj;
    const int bcol_ = (bt & 1) * 8;

    const int q0 = (gridDim.x - 1 - blockIdx.x) * 128;  // heavy blocks first
    const int h  = blockIdx.y;
    const int kh = h >> 2;
    const int qw = q0 + wr;

    // ---- stage Q (scaled) into Ps, load A-fragments once ----
    {
        int row = tid >> 1;
        int d0  = (tid & 1) * 32;
        const float* qrow = Q + (size_t)(q0 + row) * QKVW + h * HD_ + d0;
        #pragma unroll
        for (int i = 0; i < 4; i++) {
            float4 u = *(const float4*)(qrow + 8 * i);
            float4 v = *(const float4*)(qrow + 8 * i + 4);
            uint4 hh = make_uint4(pack_h2(u.x * 0.125f, u.y * 0.125f),
                                  pack_h2(u.z * 0.125f, u.w * 0.125f),
                                  pack_h2(v.x * 0.125f, v.y * 0.125f),
                                  pack_h2(v.z * 0.125f, v.w * 0.125f));
            *(uint4*)&Ps[row * FST + d0 + 8 * i] = hh;
        }
    }
    __syncthreads();

    uint32_t qf[4][4];
    #pragma unroll
    for (int ks = 0; ks < 4; ks++) {
        const __half* p = &Ps[(wr + l15) * FST + ks * 16 + lhi * 8];
        ldsm_x4(qf[ks][0], qf[ks][1], qf[ks][2], qf[ks][3],
                (uint32_t)__cvta_generic_to_shared(p));
    }
    __syncthreads();

    float of[8][4];
    #pragma unroll
    for (int nf = 0; nf < 8; nf++)
        #pragma unroll
        for (int r = 0; r < 4; r++) of[nf][r] = 0.f;
    float m0 = -1e30f, m1 = -1e30f, l0 = 0.f, l1 = 0.f;

    const int kv_r = tid >> 2;
    const int kv_c = (tid & 3) * 16;

    for (int n0 = 0; n0 <= q0 + 64; n0 += 64) {
        {
            const __half* ksrc = KV16 + (size_t)(n0 + kv_r) * KVW + kh * HD_ + kv_c;
            const __half* vsrc = ksrc + KD_;
            *(uint4*)&Ks[kv_r * FST + kv_c]     = *(const uint4*)ksrc;
            *(uint4*)&Ks[kv_r * FST + kv_c + 8] = *(const uint4*)(ksrc + 8);
            *(uint4*)&Vs[kv_r * FST + kv_c]     = *(const uint4*)vsrc;
            *(uint4*)&Vs[kv_r * FST + kv_c + 8] = *(const uint4*)(vsrc + 8);
        }
        __syncthreads();

        if (n0 <= qw + 15) {
            float sf[8][4];
            #pragma unroll
            for (int nf = 0; nf < 8; nf++)
                #pragma unroll
                for (int r = 0; r < 4; r++) sf[nf][r] = 0.f;

            #pragma unroll
            for (int ks = 0; ks < 4; ks++) {
                uint32_t bf[4][4];
                #pragma unroll
                for (int nb = 0; nb < 4; nb++) {
                    const __half* p = &Ks[(nb * 16 + brow_) * FST + ks * 16 + bcol_];
                    ldsm_x4(bf[nb][0], bf[nb][1], bf[nb][2], bf[nb][3],
                            (uint32_t)__cvta_generic_to_shared(p));
                }
                #pragma unroll
                for (int nf = 0; nf < 8; nf++) {
                    int nb = nf >> 1, o = (nf & 1) * 2;
                    mma_f16(sf[nf][0], sf[nf][1], sf[nf][2], sf[nf][3],
                            qf[ks][0], qf[ks][1], qf[ks][2], qf[ks][3],
                            bf[nb][o], bf[nb][o + 1]);
                }
            }

            if (n0 + 63 > qw) {
                int r0 = qw + g - n0;
                int r1 = r0 + 8;
                #pragma unroll
                for (int nf = 0; nf < 8; nf++) {
                    int c = 8 * nf + 2 * tg;
                    if (c     > r0) sf[nf][0] = -1e30f;
                    if (c + 1 > r0) sf[nf][1] = -1e30f;
                    if (c     > r1) sf[nf][2] = -1e30f;
                    if (c + 1 > r1) sf[nf][3] = -1e30f;
                }
            }

            {
                float tm0 = -1e30f, tm1 = -1e30f;
                #pragma unroll
                for (int nf = 0; nf < 8; nf++) {
                    tm0 = fmaxf(tm0, fmaxf(sf[nf][0], sf[nf][1]));
                    tm1 = fmaxf(tm1, fmaxf(sf[nf][2], sf[nf][3]));
                }
                #pragma unroll
                for (int o = 1; o <= 2; o <<= 1) {
                    tm0 = fmaxf(tm0, __shfl_xor_sync(0xffffffffu, tm0, o));
                    tm1 = fmaxf(tm1, __shfl_xor_sync(0xffffffffu, tm1, o));
                }
                float mn0 = fmaxf(m0, tm0);
                float mn1 = fmaxf(m1, tm1);
                float cor0 = __expf(m0 - mn0);
                float cor1 = __expf(m1 - mn1);
                float rs0 = 0.f, rs1 = 0.f;
                #pragma unroll
                for (int nf = 0; nf < 8; nf++) {
                    float p0 = __expf(sf[nf][0] - mn0);
                    float p1 = __expf(sf[nf][1] - mn0);
                    float p2 = __expf(sf[nf][2] - mn1);
                    float p3 = __expf(sf[nf][3] - mn1);
                    sf[nf][0] = p0; sf[nf][1] = p1; sf[nf][2] = p2; sf[nf][3] = p3;
                    rs0 += p0 + p1; rs1 += p2 + p3;
                }
                #pragma unroll
                for (int o = 1; o <= 2; o <<= 1) {
                    rs0 += __shfl_xor_sync(0xffffffffu, rs0, o);
                    rs1 += __shfl_xor_sync(0xffffffffu, rs1, o);
                }
                l0 = l0 * cor0 + rs0;  m0 = mn0;
                l1 = l1 * cor1 + rs1;  m1 = mn1;
                #pragma unroll
                for (int nf = 0; nf < 8; nf++) {
                    of[nf][0] *= cor0; of[nf][1] *= cor0;
                    of[nf][2] *= cor1; of[nf][3] *= cor1;
                }
            }

            #pragma unroll
            for (int nf = 0; nf < 8; nf++) {
                int c = 8 * nf + 2 * tg;
                *(uint32_t*)&Ps[(wr + g)     * FST + c] = pack_h2(sf[nf][0], sf[nf][1]);
                *(uint32_t*)&Ps[(wr + g + 8) * FST + c] = pack_h2(sf[nf][2], sf[nf][3]);
            }
            __syncwarp();

            #pragma unroll
            for (int ks = 0; ks < 4; ks++) {
                uint32_t af[4];
                {
                    const __half* p = &Ps[(wr + l15) * FST + ks * 16 + lhi * 8];
                    ldsm_x4(af[0], af[1], af[2], af[3],
                            (uint32_t)__cvta_generic_to_shared(p));
                }
                #pragma unroll
                for (int nb = 0; nb < 4; nb++) {
                    uint32_t vf[4];
                    const __half* p = &Vs[(ks * 16 + l15) * FST + nb * 16 + lhi * 8];
                    ldsm_x4_t(vf[0], vf[1], vf[2], vf[3],
                              (uint32_t)__cvta_generic_to_shared(p));
                    mma_f16(of[2*nb][0], of[2*nb][1], of[2*nb][2], of[2*nb][3],
                            af[0], af[1], af[2], af[3], vf[0], vf[1]);
                    mma_f16(of[2*nb+1][0], of[2*nb+1][1], of[2*nb+1][2], of[2*nb+1][3],
                            af[0], af[1], af[2], af[3], vf[2], vf[3]);
                }
            }
        }
        __syncthreads();
    }

    // ---- finalize: write fp16 att ----
    {
        float inv0 = 1.f / l0;
        float inv1 = 1.f / l1;
        __half* o_r0 = O16 + (size_t)(q0 + wr + g)     * D_ + h * HD_;
        __half* o_r1 = O16 + (size_t)(q0 + wr + g + 8) * D_ + h * HD_;
        #pragma unroll
        for (int nf = 0; nf < 8; nf++) {
            int c = 8 * nf + 2 * tg;
            *(uint32_t*)&o_r0[c] = pack_h2(of[nf][0] * inv0, of[nf][1] * inv0);
            *(uint32_t*)&o_r1[c] = pack_h2(of[nf][2] * inv1, of[nf][3] * inv1);
        }
    }
}

// ---------------------------------------------------------------------------
// Launch
// ---------------------------------------------------------------------------
extern "C" void kernel_launch(void* const* d_in, const int* in_sizes, int n_in,
                              void* d_out, int out_size)
{
    const float* x    = (const float*)d_in[0];
    const float* cosp = (const float*)d_in[1];
    const float* sinp = (const float*)d_in[2];
    // d_in[3] = mask (causal tril, recomputed analytically) — unused
    const float* Wq   = (const float*)d_in[4];
    const float* Wk   = (const float*)d_in[5];
    const float* Wv   = (const float*)d_in[6];
    const float* Wo   = (const float*)d_in[7];
    const float* qn_w = (const float*)d_in[8];
    const float* kn_w = (const float*)d_in[9];
    float* out = (float*)d_out;

    float* qkvp;
    __half *kv16p, *att16p, *x16p, *wq16p, *wk16p, *wv16p, *wo16p;
    cudaGetSymbolAddress((void**)&qkvp,  g_qkv);
    cudaGetSymbolAddress((void**)&kv16p, g_kv16);
    cudaGetSymbolAddress((void**)&att16p, g_att16);
    cudaGetSymbolAddress((void**)&x16p,  g_x16);
    cudaGetSymbolAddress((void**)&wq16p, g_wq16);
    cudaGetSymbolAddress((void**)&wk16p, g_wk16);
    cudaGetSymbolAddress((void**)&wv16p, g_wv16);
    cudaGetSymbolAddress((void**)&wo16p, g_wo16);

    // fp32 -> fp16 input conversions
    f2h_kernel<<<(S_ * D_) / 1024, 256>>>(x, x16p, S_ * D_);
    f2h_kernel<<<(D_ * D_) / 1024, 256>>>(Wq, wq16p, D_ * D_);
    f2h_kernel<<<(D_ * KD_) / 1024, 256>>>(Wk, wk16p, D_ * KD_);
    f2h_kernel<<<(D_ * KD_) / 1024, 256>>>(Wv, wv16p, D_ * KD_);
    f2h_kernel<<<(D_ * D_) / 1024, 256>>>(Wo, wo16p, D_ * D_);

    // Fused QKV projection (fp16 in, cp.async pipelined)
    qkv_gemm_kernel<<<dim3(24, S_ / 128), 256>>>(x16p, wq16p, wk16p, wv16p, qkvp);

    // rmsnorm + RoPE; K also mirrored to fp16 kv buffer
    rms_rope_kernel<<<S_, 256>>>(qkvp,      QKVW, D_,  qn_w, cosp, sinp,
                                 (half*)nullptr, 0);
    rms_rope_kernel<<<S_, 256>>>(qkvp + D_, QKVW, KD_, kn_w, cosp, sinp,
                                 kv16p, KVW);
    // V -> fp16 kv buffer
    v2h_kernel<<<S_, 256>>>(qkvp + D_ + KD_, kv16p);

    // Causal GQA flash attention (fp16 mma + ldmatrix, BM=128) -> fp16 att
    flash_mma_kernel<<<dim3(S_ / 128, H_), 256>>>(qkvp, kv16p, att16p);

    // Output projection (fp16 in, cp.async pipelined)
    wo_gemm_kernel<<<dim3(16, 16), 256>>>(att16p, wo16p, out);
}

// round 17
// speedup vs baseline: 7.5538x; 1.0860x over previous
#include <cuda_runtime.h>
#include <cuda_fp16.h>
#include <cuda_bf16.h>
#include <cstdint>

// Problem constants
#define S_   2048
#define D_   2048
#define H_   32
#define KVH_ 8
#define HD_  64
#define KD_  512    // KVH*HD
#define QKVW 3072   // packed qkv row width: q[0,2048) k[2048,2560) v[2560,3072)
#define KVW  1024   // packed fp16 kv row width: k[0,512) v[512,1024)
#define EPS_ 1e-5f
#define SD_  (S_ * D_)     // 4194304
#define KDD_ (D_ * KD_)    // 1048576

// ---------------------------------------------------------------------------
// Scratch (no allocations allowed -> __device__ globals)
// ---------------------------------------------------------------------------
__device__ float  g_qkv[S_ * QKVW];   // packed q|k|v after proj (later norm+rope)
__device__ __half g_kv16[S_ * KVW];   // fp16 k (rope'd) | v
__device__ __half g_att16[S_ * D_];   // attention output, fp16 (A of Wo gemm)
__device__ __half g_x16[S_ * D_];     // x in fp16
__device__ __half g_wq16[D_ * D_];
__device__ __half g_wk16[D_ * KD_];
__device__ __half g_wv16[D_ * KD_];
__device__ __half g_wo16[D_ * D_];

// ---------------------------------------------------------------------------
// Helpers
// ---------------------------------------------------------------------------
__device__ __forceinline__ uint32_t pack_h2(float lo, float hi) {
    __half2 h = __floats2half2_rn(lo, hi);
    return *reinterpret_cast<uint32_t*>(&h);
}

__device__ __forceinline__ void mma_f16(
    float& c0, float& c1, float& c2, float& c3,
    uint32_t a0, uint32_t a1, uint32_t a2, uint32_t a3,
    uint32_t b0, uint32_t b1)
{
    asm volatile(
        "mma.sync.aligned.m16n8k16.row.col.f32.f16.f16.f32 "
        "{%0,%1,%2,%3}, {%4,%5,%6,%7}, {%8,%9}, {%0,%1,%2,%3};\n"
        : "+f"(c0), "+f"(c1), "+f"(c2), "+f"(c3)
        : "r"(a0), "r"(a1), "r"(a2), "r"(a3), "r"(b0), "r"(b1));
}

__device__ __forceinline__ void ldsm_x4(
    uint32_t& r0, uint32_t& r1, uint32_t& r2, uint32_t& r3, uint32_t addr)
{
    asm volatile("ldmatrix.sync.aligned.m8n8.x4.shared.b16 {%0,%1,%2,%3}, [%4];\n"
                 : "=r"(r0), "=r"(r1), "=r"(r2), "=r"(r3) : "r"(addr));
}

__device__ __forceinline__ void ldsm_x4_t(
    uint32_t& r0, uint32_t& r1, uint32_t& r2, uint32_t& r3, uint32_t addr)
{
    asm volatile("ldmatrix.sync.aligned.m8n8.x4.trans.shared.b16 {%0,%1,%2,%3}, [%4];\n"
                 : "=r"(r0), "=r"(r1), "=r"(r2), "=r"(r3) : "r"(addr));
}

__device__ __forceinline__ void cp_async16(uint32_t smem_addr, const void* gptr) {
    asm volatile("cp.async.ca.shared.global [%0], [%1], 16;\n"
                 :: "r"(smem_addr), "l"(gptr));
}
#define CP_COMMIT() asm volatile("cp.async.commit_group;\n" ::: "memory")
#define CP_WAIT0()  asm volatile("cp.async.wait_group 0;\n" ::: "memory")

// ---------------------------------------------------------------------------
// Bulk fp32->fp16 for x, Wq, Wk, Wv, Wo in ONE launch (range-partitioned).
// Total elements: 3*SD_ + 2*KDD_ = 14680064 -> exactly 14336 blocks of 256x4.
// ---------------------------------------------------------------------------
__global__ __launch_bounds__(256) void f2h_all_kernel(
    const float* __restrict__ x,  const float* __restrict__ wq,
    const float* __restrict__ wk, const float* __restrict__ wv,
    const float* __restrict__ wo,
    __half* __restrict__ x16,  __half* __restrict__ wq16,
    __half* __restrict__ wk16, __half* __restrict__ wv16,
    __half* __restrict__ wo16)
{
    int i = (blockIdx.x * 256 + threadIdx.x) * 4;
    const float* src; __half* dst; int off;
    if      (i < SD_)              { src = x;  dst = x16;  off = i; }
    else if (i < 2*SD_)            { src = wq; dst = wq16; off = i - SD_; }
    else if (i < 2*SD_ + KDD_)     { src = wk; dst = wk16; off = i - 2*SD_; }
    else if (i < 2*SD_ + 2*KDD_)   { src = wv; dst = wv16; off = i - 2*SD_ - KDD_; }
    else                           { src = wo; dst = wo16; off = i - 2*SD_ - 2*KDD_; }
    float4 v = *(const float4*)(src + off);
    *(uint2*)(dst + off) = make_uint2(pack_h2(v.x, v.y), pack_h2(v.z, v.w));
}

// ---------------------------------------------------------------------------
// FP16-input tensor-core GEMM core with cp.async 2-stage double buffering.
// (validated R12/R13)
// ---------------------------------------------------------------------------
#define GK  32
#define AST 40
#define BST 136

__device__ __forceinline__ void hgemm16_core(
    const __half* __restrict__ A, int lda,
    const __half* __restrict__ B, int ldb,
    float* __restrict__ C, int ldc,
    int K, int brow, int bcol, int ccol)
{
    __shared__ __half As[2][128 * AST];
    __shared__ __half Bs[2][GK * BST];

    const int tid  = threadIdx.x;
    const int wid  = tid >> 5;
    const int lane = tid & 31;
    const int g    = lane >> 2;
    const int tg   = lane & 3;
    const int wm   = (wid & 1) * 64;
    const int wn   = (wid >> 1) * 32;
    const int l15  = lane & 15;
    const int lhi  = lane >> 4;

    const int a_r0 = tid >> 2, a_co = (tid & 3) * 8;
    const int b_r0 = tid >> 4, b_co = (tid & 15) * 8;

    float c[4][4][4];
    #pragma unroll
    for (int i = 0; i < 4; i++)
        #pragma unroll
        for (int j = 0; j < 4; j++)
            #pragma unroll
            for (int r = 0; r < 4; r++) c[i][j][r] = 0.f;

    const int nit = K / GK;

    auto issue = [&](int buf, int k0) {
        cp_async16((uint32_t)__cvta_generic_to_shared(&As[buf][a_r0 * AST + a_co]),
                   A + (size_t)(brow + a_r0) * lda + k0 + a_co);
        cp_async16((uint32_t)__cvta_generic_to_shared(&As[buf][(a_r0 + 64) * AST + a_co]),
                   A + (size_t)(brow + a_r0 + 64) * lda + k0 + a_co);
        cp_async16((uint32_t)__cvta_generic_to_shared(&Bs[buf][b_r0 * BST + b_co]),
                   B + (size_t)(k0 + b_r0) * ldb + bcol + b_co);
        cp_async16((uint32_t)__cvta_generic_to_shared(&Bs[buf][(b_r0 + 16) * BST + b_co]),
                   B + (size_t)(k0 + b_r0 + 16) * ldb + bcol + b_co);
        CP_COMMIT();
    };

    issue(0, 0);
    int buf = 0;

    for (int it = 0; it < nit; it++) {
        CP_WAIT0();
        __syncthreads();
        if (it + 1 < nit) issue(buf ^ 1, (it + 1) * GK);

        const __half* Ab = As[buf];
        const __half* Bb = Bs[buf];
        #pragma unroll
        for (int ks = 0; ks < 2; ks++) {
            uint32_t af[4][4];
            #pragma unroll
            for (int mf = 0; mf < 4; mf++) {
                const __half* p = &Ab[(wm + mf * 16 + l15) * AST + ks * 16 + lhi * 8];
                ldsm_x4(af[mf][0], af[mf][1], af[mf][2], af[mf][3],
                        (uint32_t)__cvta_generic_to_shared(p));
            }
            uint32_t bf[2][4];
            #pragma unroll
            for (int nb = 0; nb < 2; nb++) {
                const __half* p = &Bb[(ks * 16 + l15) * BST + wn + nb * 16 + lhi * 8];
                ldsm_x4_t(bf[nb][0], bf[nb][1], bf[nb][2], bf[nb][3],
                          (uint32_t)__cvta_generic_to_shared(p));
            }
            #pragma unroll
            for (int mf = 0; mf < 4; mf++)
                #pragma unroll
                for (int nf = 0; nf < 4; nf++) {
                    int nb = nf >> 1, hi = (nf & 1) * 2;
                    mma_f16(c[mf][nf][0], c[mf][nf][1], c[mf][nf][2], c[mf][nf][3],
                            af[mf][0], af[mf][1], af[mf][2], af[mf][3],
                            bf[nb][hi], bf[nb][hi + 1]);
                }
        }
        buf ^= 1;
    }

    #pragma unroll
    for (int mf = 0; mf < 4; mf++) {
        int r0 = brow + wm + 16 * mf + g;
        #pragma unroll
        for (int nf = 0; nf < 4; nf++) {
            int cc = ccol + wn + 8 * nf + 2 * tg;
            *(float2*)&C[(size_t)r0 * ldc + cc]       = make_float2(c[mf][nf][0], c[mf][nf][1]);
            *(float2*)&C[(size_t)(r0 + 8) * ldc + cc] = make_float2(c[mf][nf][2], c[mf][nf][3]);
        }
    }
}

__global__ __launch_bounds__(256, 2) void qkv_gemm_kernel(
    const __half* __restrict__ x16,
    const __half* __restrict__ Wq16, const __half* __restrict__ Wk16,
    const __half* __restrict__ Wv16, float* __restrict__ qkv)
{
    const int bx = blockIdx.x;
    const __half* B; int ldb, bcol;
    if (bx < 16)      { B = Wq16; ldb = D_;  bcol = bx * 128; }
    else if (bx < 20) { B = Wk16; ldb = KD_; bcol = (bx - 16) * 128; }
    else              { B = Wv16; ldb = KD_; bcol = (bx - 20) * 128; }
    hgemm16_core(x16, D_, B, ldb, qkv, QKVW, D_, blockIdx.y * 128, bcol, bx * 128);
}

__global__ __launch_bounds__(256, 2) void wo_gemm_kernel(
    const __half* __restrict__ A16, const __half* __restrict__ Wo16,
    float* __restrict__ C)
{
    hgemm16_core(A16, D_, Wo16, D_, C, D_, D_,
                 blockIdx.y * 128, blockIdx.x * 128, blockIdx.x * 128);
}

// ---------------------------------------------------------------------------
// Fused rmsnorm + RoPE for Q and K (+V fp16 convert), one launch.
// grid = (S, 2): y=0 -> q row (width D_); y=1 -> k row (width KD_,
// mirrored to fp16 kv) + v row fp16 convert.
// ---------------------------------------------------------------------------
__global__ __launch_bounds__(256) void rms_rope_qkv_kernel(
    float* __restrict__ qkv,
    const float* __restrict__ qn_w, const float* __restrict__ kn_w,
    const float* __restrict__ cosp, const float* __restrict__ sinp,
    __half* __restrict__ kv16)
{
    const int s   = blockIdx.x;
    const bool isq = (blockIdx.y == 0);
    const int tid = threadIdx.x;

    float* row = qkv + (size_t)s * QKVW + (isq ? 0 : D_);
    const int width = isq ? D_ : KD_;
    const float* w = isq ? qn_w : kn_w;
    __half* o16 = isq ? nullptr : kv16 + (size_t)s * KVW;

    // V fp32 -> fp16 (done by the k-block; independent of rms below)
    if (!isq) {
        const float* vsrc = qkv + (size_t)s * QKVW + D_ + KD_;
        float2 u = *(const float2*)(vsrc + tid * 2);
        *(uint32_t*)&kv16[(size_t)s * KVW + KD_ + tid * 2] = pack_h2(u.x, u.y);
    }

    float ss = 0.f;
    for (int i = tid; i < width; i += 256) {
        float v = row[i];
        ss += v * v;
    }
    #pragma unroll
    for (int o = 16; o; o >>= 1) ss += __shfl_xor_sync(0xffffffffu, ss, o);

    __shared__ float red[8];
    __shared__ float s_r;
    if ((tid & 31) == 0) red[tid >> 5] = ss;
    __syncthreads();
    if (tid == 0) {
        float t = 0.f;
        #pragma unroll
        for (int i = 0; i < 8; i++) t += red[i];
        s_r = rsqrtf(t / (float)width + EPS_);
    }
    __syncthreads();
    const float r = s_r;

    const float* cr = cosp + (size_t)s * HD_;
    const float* sr = sinp + (size_t)s * HD_;
    const int npairs = width >> 1;
    for (int p = tid; p < npairs; p += 256) {
        int head = p >> 5;
        int d    = p & 31;
        int i0 = head * HD_ + d;
        int i1 = i0 + 32;
        float v0 = row[i0] * r * w[i0];
        float v1 = row[i1] * r * w[i1];
        float c0 = cr[d],      s0 = sr[d];
        float c1 = cr[d + 32], s1 = sr[d + 32];
        float o0 = v0 * c0 - v1 * s0;
        float o1 = v1 * c1 + v0 * s1;
        row[i0] = o0;
        row[i1] = o1;
        if (o16) {
            o16[i0] = __float2half(o0);
            o16[i1] = __float2half(o1);
        }
    }
}

// ---------------------------------------------------------------------------
// Flash attention v4: fp16 mma, BM=128, cp.async double-buffered K/V,
// P kept in registers (C-frag -> A-frag identity; no smem roundtrip),
// Q fragments loaded directly from gmem. grid = (S/128, H).
// smem = 2*(Ks+Vs) = 36.9 KB; 2 CTAs/SM.
// ---------------------------------------------------------------------------
#define FST 72

__global__ __launch_bounds__(256, 2) void flash_mma_kernel(
    const float* __restrict__ Q, const __half* __restrict__ KV16,
    __half* __restrict__ O16)
{
    __shared__ __half Ks[2][64 * FST];
    __shared__ __half Vs[2][64 * FST];

    const int tid  = threadIdx.x;
    const int wid  = tid >> 5;
    const int lane = tid & 31;
    const int g    = lane >> 2;
    const int tg   = lane & 3;
    const int wr   = wid * 16;
    const int l15  = lane & 15;
    const int lhi  = lane >> 4;
    const int bt   = lane >> 3;
    const int bj   = lane & 7;
    const int brow_ = ((bt >> 1) * 8) + bj;
    const int bcol_ = (bt & 1) * 8;

    const int q0 = (gridDim.x - 1 - blockIdx.x) * 128;  // heavy blocks first
    const int h  = blockIdx.y;
    const int kh = h >> 2;
    const int qw = q0 + wr;

    // ---- Q A-fragments loaded directly from gmem (pre-scaled) ----
    uint32_t qf[4][4];
    {
        const float* q_r0 = Q + (size_t)(qw + g)     * QKVW + h * HD_;
        const float* q_r1 = Q + (size_t)(qw + g + 8) * QKVW + h * HD_;
        #pragma unroll
        for (int ks = 0; ks < 4; ks++) {
            float2 u0 = *(const float2*)(q_r0 + 16 * ks + 2 * tg);
            float2 u1 = *(const float2*)(q_r1 + 16 * ks + 2 * tg);
            float2 u2 = *(const float2*)(q_r0 + 16 * ks + 8 + 2 * tg);
            float2 u3 = *(const float2*)(q_r1 + 16 * ks + 8 + 2 * tg);
            qf[ks][0] = pack_h2(u0.x * 0.125f, u0.y * 0.125f);
            qf[ks][1] = pack_h2(u1.x * 0.125f, u1.y * 0.125f);
            qf[ks][2] = pack_h2(u2.x * 0.125f, u2.y * 0.125f);
            qf[ks][3] = pack_h2(u3.x * 0.125f, u3.y * 0.125f);
        }
    }

    float of[8][4];
    #pragma unroll
    for (int nf = 0; nf < 8; nf++)
        #pragma unroll
        for (int r = 0; r < 4; r++) of[nf][r] = 0.f;
    float m0 = -1e30f, m1 = -1e30f, l0 = 0.f, l1 = 0.f;

    // K/V staging indices
    const int kv_r = tid >> 2;
    const int kv_c = (tid & 3) * 16;

    auto issue = [&](int buf, int n0) {
        const __half* ksrc = KV16 + (size_t)(n0 + kv_r) * KVW + kh * HD_ + kv_c;
        cp_async16((uint32_t)__cvta_generic_to_shared(&Ks[buf][kv_r * FST + kv_c]),     ksrc);
        cp_async16((uint32_t)__cvta_generic_to_shared(&Ks[buf][kv_r * FST + kv_c + 8]), ksrc + 8);
        cp_async16((uint32_t)__cvta_generic_to_shared(&Vs[buf][kv_r * FST + kv_c]),     ksrc + KD_);
        cp_async16((uint32_t)__cvta_generic_to_shared(&Vs[buf][kv_r * FST + kv_c + 8]), ksrc + KD_ + 8);
        CP_COMMIT();
    };

    const int ntiles = q0 / 64 + 2;   // kv tiles 0, 64, ..., q0+64
    issue(0, 0);
    int buf = 0;

    for (int it = 0; it < ntiles; it++) {
        const int n0 = it * 64;
        CP_WAIT0();
        __syncthreads();
        if (it + 1 < ntiles) issue(buf ^ 1, n0 + 64);

        if (n0 <= qw + 15) {   // warp not fully masked
            const __half* Kb = Ks[buf];
            const __half* Vb = Vs[buf];

            // ---- S = Q K^T (16x64 per warp) ----
            float sf[8][4];
            #pragma unroll
            for (int nf = 0; nf < 8; nf++)
                #pragma unroll
                for (int r = 0; r < 4; r++) sf[nf][r] = 0.f;

            #pragma unroll
            for (int ks = 0; ks < 4; ks++) {
                uint32_t bf[4][4];
                #pragma unroll
                for (int nb = 0; nb < 4; nb++) {
                    const __half* p = &Kb[(nb * 16 + brow_) * FST + ks * 16 + bcol_];
                    ldsm_x4(bf[nb][0], bf[nb][1], bf[nb][2], bf[nb][3],
                            (uint32_t)__cvta_generic_to_shared(p));
                }
                #pragma unroll
                for (int nf = 0; nf < 8; nf++) {
                    int nb = nf >> 1, o = (nf & 1) * 2;
                    mma_f16(sf[nf][0], sf[nf][1], sf[nf][2], sf[nf][3],
                            qf[ks][0], qf[ks][1], qf[ks][2], qf[ks][3],
                            bf[nb][o], bf[nb][o + 1]);
                }
            }

            // ---- causal mask (diagonal tiles) ----
            if (n0 + 63 > qw) {
                int r0 = qw + g - n0;
                int r1 = r0 + 8;
                #pragma unroll
                for (int nf = 0; nf < 8; nf++) {
                    int c = 8 * nf + 2 * tg;
                    if (c     > r0) sf[nf][0] = -1e30f;
                    if (c + 1 > r0) sf[nf][1] = -1e30f;
                    if (c     > r1) sf[nf][2] = -1e30f;
                    if (c + 1 > r1) sf[nf][3] = -1e30f;
                }
            }

            // ---- online softmax ----
            {
                float tm0 = -1e30f, tm1 = -1e30f;
                #pragma unroll
                for (int nf = 0; nf < 8; nf++) {
                    tm0 = fmaxf(tm0, fmaxf(sf[nf][0], sf[nf][1]));
                    tm1 = fmaxf(tm1, fmaxf(sf[nf][2], sf[nf][3]));
                }
                #pragma unroll
                for (int o = 1; o <= 2; o <<= 1) {
                    tm0 = fmaxf(tm0, __shfl_xor_sync(0xffffffffu, tm0, o));
                    tm1 = fmaxf(tm1, __shfl_xor_sync(0xffffffffu, tm1, o));
                }
                float mn0 = fmaxf(m0, tm0);
                float mn1 = fmaxf(m1, tm1);
                float cor0 = __expf(m0 - mn0);
                float cor1 = __expf(m1 - mn1);
                float rs0 = 0.f, rs1 = 0.f;
                #pragma unroll
                for (int nf = 0; nf < 8; nf++) {
                    float p0 = __expf(sf[nf][0] - mn0);
                    float p1 = __expf(sf[nf][1] - mn0);
                    float p2 = __expf(sf[nf][2] - mn1);
                    float p3 = __expf(sf[nf][3] - mn1);
                    sf[nf][0] = p0; sf[nf][1] = p1; sf[nf][2] = p2; sf[nf][3] = p3;
                    rs0 += p0 + p1; rs1 += p2 + p3;
                }
                #pragma unroll
                for (int o = 1; o <= 2; o <<= 1) {
                    rs0 += __shfl_xor_sync(0xffffffffu, rs0, o);
                    rs1 += __shfl_xor_sync(0xffffffffu, rs1, o);
                }
                l0 = l0 * cor0 + rs0;  m0 = mn0;
                l1 = l1 * cor1 + rs1;  m1 = mn1;
                #pragma unroll
                for (int nf = 0; nf < 8; nf++) {
                    of[nf][0] *= cor0; of[nf][1] *= cor0;
                    of[nf][2] *= cor1; of[nf][3] *= cor1;
                }
            }

            // ---- O += P @ V : P stays in registers (C-frag == A-frag) ----
            #pragma unroll
            for (int ks = 0; ks < 4; ks++) {
                uint32_t a0 = pack_h2(sf[2*ks][0],     sf[2*ks][1]);
                uint32_t a1 = pack_h2(sf[2*ks][2],     sf[2*ks][3]);
                uint32_t a2 = pack_h2(sf[2*ks + 1][0], sf[2*ks + 1][1]);
                uint32_t a3 = pack_h2(sf[2*ks + 1][2], sf[2*ks + 1][3]);
                #pragma unroll
                for (int nb = 0; nb < 4; nb++) {
                    uint32_t vf[4];
                    const __half* p = &Vb[(ks * 16 + l15) * FST + nb * 16 + lhi * 8];
                    ldsm_x4_t(vf[0], vf[1], vf[2], vf[3],
                              (uint32_t)__cvta_generic_to_shared(p));
                    mma_f16(of[2*nb][0], of[2*nb][1], of[2*nb][2], of[2*nb][3],
                            a0, a1, a2, a3, vf[0], vf[1]);
                    mma_f16(of[2*nb+1][0], of[2*nb+1][1], of[2*nb+1][2], of[2*nb+1][3],
                            a0, a1, a2, a3, vf[2], vf[3]);
                }
            }
        }
        __syncthreads();   // all reads of buf done before it is re-issued
        buf ^= 1;
    }

    // ---- finalize: write fp16 att ----
    {
        float inv0 = 1.f / l0;
        float inv1 = 1.f / l1;
        __half* o_r0 = O16 + (size_t)(qw + g)     * D_ + h * HD_;
        __half* o_r1 = O16 + (size_t)(qw + g + 8) * D_ + h * HD_;
        #pragma unroll
        for (int nf = 0; nf < 8; nf++) {
            int c = 8 * nf + 2 * tg;
            *(uint32_t*)&o_r0[c] = pack_h2(of[nf][0] * inv0, of[nf][1] * inv0);
            *(uint32_t*)&o_r1[c] = pack_h2(of[nf][2] * inv1, of[nf][3] * inv1);
        }
    }
}

// ---------------------------------------------------------------------------
// Launch
// ---------------------------------------------------------------------------
extern "C" void kernel_launch(void* const* d_in, const int* in_sizes, int n_in,
                              void* d_out, int out_size)
{
    const float* x    = (const float*)d_in[0];
    const float* cosp = (const float*)d_in[1];
    const float* sinp = (const float*)d_in[2];
    // d_in[3] = mask (causal tril, recomputed analytically) — unused
    const float* Wq   = (const float*)d_in[4];
    const float* Wk   = (const float*)d_in[5];
    const float* Wv   = (const float*)d_in[6];
    const float* Wo   = (const float*)d_in[7];
    const float* qn_w = (const float*)d_in[8];
    const float* kn_w = (const float*)d_in[9];
    float* out = (float*)d_out;

    float* qkvp;
    __half *kv16p, *att16p, *x16p, *wq16p, *wk16p, *wv16p, *wo16p;
    cudaGetSymbolAddress((void**)&qkvp,  g_qkv);
    cudaGetSymbolAddress((void**)&kv16p, g_kv16);
    cudaGetSymbolAddress((void**)&att16p, g_att16);
    cudaGetSymbolAddress((void**)&x16p,  g_x16);
    cudaGetSymbolAddress((void**)&wq16p, g_wq16);
    cudaGetSymbolAddress((void**)&wk16p, g_wk16);
    cudaGetSymbolAddress((void**)&wv16p, g_wv16);
    cudaGetSymbolAddress((void**)&wo16p, g_wo16);

    // fp32 -> fp16 conversions, one launch
    const int total = 3 * SD_ + 2 * KDD_;
    f2h_all_kernel<<<total / 1024, 256>>>(x, Wq, Wk, Wv, Wo,
                                          x16p, wq16p, wk16p, wv16p, wo16p);

    // Fused QKV projection (fp16 in, cp.async pipelined)
    qkv_gemm_kernel<<<dim3(24, S_ / 128), 256>>>(x16p, wq16p, wk16p, wv16p, qkvp);

    // rmsnorm + RoPE for Q and K (+ V fp16 convert), one launch
    rms_rope_qkv_kernel<<<dim3(S_, 2), 256>>>(qkvp, qn_w, kn_w, cosp, sinp, kv16p);

    // Causal GQA flash attention (fp16 mma, register P, cp.async K/V)
    flash_mma_kernel<<<dim3(S_ / 128, H_), 256>>>(qkvp, kv16p, att16p);

    // Output projection (fp16 in, cp.async pipelined)
    wo_gemm_kernel<<<dim3(16, 16), 256>>>(att16p, wo16p, out);
}